// round 5
// baseline (speedup 1.0000x reference)
#include <cuda_runtime.h>
#include <cstdint>

#define B 8
#define C 256
#define N 3136
#define NQ (N/4)
#define NC 50
#define TILE 128
#define KT 16
#define NT 25                  // ceil(N/128)
#define NPAIRS (NT*(NT+1)/2)   // 325 upper-triangle tile pairs
#define SP 136                 // smem pitch for tf32 tiles (conflict-free frags)
#define PC 132                 // straight staging pitch
#define PT 36                  // transposed staging pitch
#define SMEM_FLOATS 8832       // max(4*16*136=8704, 32*132 + 128*36 = 8832)

// ---------------- scratch (static device globals: allocation-guard safe) ----
__device__ float    g_d2[(size_t)B * N * N];
__device__ float    g_sq[B * N];
__device__ float    g_dens[B * N];
__device__ float    g_score[B * N];
__device__ unsigned g_maxb[B];
__device__ int      g_idx[B * NC];

// ---------------- threefry-2x32 (JAX-compatible) ---------------------------
__device__ __forceinline__ uint32_t rotl32(uint32_t x, int r) {
    return (x << r) | (x >> (32 - r));
}

__device__ __forceinline__ void threefry2x32_k42(uint32_t x0, uint32_t x1,
                                                 uint32_t& o0, uint32_t& o1) {
    const uint32_t ks0 = 0u;
    const uint32_t ks1 = 42u;
    const uint32_t ks2 = 0x1BD11BDAu ^ 42u;
    x0 += ks0; x1 += ks1;
#define TF_RND(r) { x0 += x1; x1 = rotl32(x1, r); x1 ^= x0; }
    TF_RND(13) TF_RND(15) TF_RND(26) TF_RND(6)
    x0 += ks1; x1 += ks2 + 1u;
    TF_RND(17) TF_RND(29) TF_RND(16) TF_RND(24)
    x0 += ks2; x1 += ks0 + 2u;
    TF_RND(13) TF_RND(15) TF_RND(26) TF_RND(6)
    x0 += ks0; x1 += ks1 + 3u;
    TF_RND(17) TF_RND(29) TF_RND(16) TF_RND(24)
    x0 += ks1; x1 += ks2 + 4u;
    TF_RND(13) TF_RND(15) TF_RND(26) TF_RND(6)
    x0 += ks2; x1 += ks0 + 5u;
#undef TF_RND
    o0 = x0; o1 = x1;
}

__device__ __forceinline__ float jax_uniform_noise(int g) {
    const int half = (B * N) / 2;  // 12544
    uint32_t lane = (g < half) ? (uint32_t)g : (uint32_t)(g - half);
    uint32_t o0, o1;
    threefry2x32_k42(lane, lane + (uint32_t)half, o0, o1);
    uint32_t bits = (g < half) ? o0 : o1;
    return __uint_as_float((bits >> 9) | 0x3F800000u) - 1.0f;
}

// ---------------- tf32 helpers ----------------------------------------------
__device__ __forceinline__ uint32_t tf32r(float x) {
    uint32_t y;
    asm("cvt.rna.tf32.f32 %0, %1;" : "=r"(y) : "f"(x));
    return y;
}

__device__ __forceinline__ void mma8(float d[4], const uint32_t a[4], const uint32_t b[2]) {
    asm volatile(
        "mma.sync.aligned.m16n8k8.row.col.f32.tf32.tf32.f32 "
        "{%0,%1,%2,%3}, {%4,%5,%6,%7}, {%8,%9}, {%0,%1,%2,%3};"
        : "+f"(d[0]), "+f"(d[1]), "+f"(d[2]), "+f"(d[3])
        : "r"(a[0]), "r"(a[1]), "r"(a[2]), "r"(a[3]), "r"(b[0]), "r"(b[1]));
}

// ---------------- kernels ---------------------------------------------------
__global__ void init_kernel() {
    int t = threadIdx.x;
    if (t < B) g_maxb[t] = 0u;
}

__global__ void sq_kernel(const float* __restrict__ x) {
    int g = blockIdx.x * blockDim.x + threadIdx.x;
    if (g >= B * N) return;
    int b = g / N, n = g % N;
    const float* p = x + (size_t)b * C * N + n;
    float s = 0.f;
#pragma unroll 8
    for (int c = 0; c < C; c++) {
        float v = p[(size_t)c * N];
        s = fmaf(v, v, s);
    }
    g_sq[g] = s;
}

// Symmetric Gram via tf32x3 tensor-core MMA.
// Block: 256 threads = 8 warps, tile 128x128. Warp w -> (wr=w>>2, wc=w&3),
// computes 64x32 (4 m-frags x 4 n-frags of m16n8k8).
__global__ __launch_bounds__(256, 1) void gram_kernel(const float* __restrict__ x) {
    const int b = blockIdx.z;

    int rem = blockIdx.x;
    int ti = 0;
    while (rem >= NT - ti) { rem -= NT - ti; ti++; }
    const int tj = ti + rem;
    const int i0 = ti * TILE;
    const int j0 = tj * TILE;

    const float* X = x + (size_t)b * C * N;
    const float* SQ = &g_sq[b * N];

    __shared__ float smem[SMEM_FLOATS];
    __shared__ float red[256];
    float* Ah = smem;
    float* Al = smem + 16 * SP;
    float* Bh = smem + 32 * SP;
    float* Bl = smem + 48 * SP;
    float* Cs  = smem;              // 32 x PC (aliases tiles; used post-mainloop)
    float* Cst = smem + 32 * PC;    // 128 x PT

    const int tid = threadIdx.x;
    const int lane = tid & 31;
    const int wid = tid >> 5;
    const int wr = wid >> 2, wc = wid & 3;
    const int wi = wr * 64, wj = wc * 32;
    const int kq = lane & 3, rr = lane >> 2;

    // global load slots (same as fp32 version)
    const int kk0 = tid >> 5;          // 0..7
    const int kk1 = kk0 + 8;
    const int f4  = tid & 31;
    const int icol = i0 + f4 * 4;
    const int jcol = j0 + f4 * 4;
    const bool iok = (icol < N);
    const bool jok = (jcol < N);

    float4 pa0, pa1, pb0, pb1;
#define LOADK(k0) {                                                          \
        pa0 = pa1 = pb0 = pb1 = make_float4(0.f, 0.f, 0.f, 0.f);             \
        if (iok) {                                                           \
            pa0 = *reinterpret_cast<const float4*>(&X[(size_t)((k0) + kk0) * N + icol]); \
            pa1 = *reinterpret_cast<const float4*>(&X[(size_t)((k0) + kk1) * N + icol]); \
        }                                                                    \
        if (jok) {                                                           \
            pb0 = *reinterpret_cast<const float4*>(&X[(size_t)((k0) + kk0) * N + jcol]); \
            pb1 = *reinterpret_cast<const float4*>(&X[(size_t)((k0) + kk1) * N + jcol]); \
        }                                                                    \
    }

    float D[4][4][4];
#pragma unroll
    for (int mf = 0; mf < 4; mf++)
#pragma unroll
        for (int nf = 0; nf < 4; nf++)
#pragma unroll
            for (int e = 0; e < 4; e++) D[mf][nf][e] = 0.f;

    LOADK(0);

#pragma unroll 1
    for (int kt = 0; kt < C / KT; kt++) {
        __syncthreads();   // previous compute finished reading smem
        // convert & store hi/lo tiles (vectorized)
        {
            const float* src[4] = {(const float*)&pa0, (const float*)&pa1,
                                   (const float*)&pb0, (const float*)&pb1};
            float* dsth[4] = {&Ah[kk0 * SP + f4 * 4], &Ah[kk1 * SP + f4 * 4],
                              &Bh[kk0 * SP + f4 * 4], &Bh[kk1 * SP + f4 * 4]};
            float* dstl[4] = {&Al[kk0 * SP + f4 * 4], &Al[kk1 * SP + f4 * 4],
                              &Bl[kk0 * SP + f4 * 4], &Bl[kk1 * SP + f4 * 4]};
#pragma unroll
            for (int s = 0; s < 4; s++) {
                float4 hv, lv;
                float* h = (float*)&hv; float* l = (float*)&lv;
#pragma unroll
                for (int e = 0; e < 4; e++) {
                    float v = src[s][e];
                    uint32_t hb = tf32r(v);
                    float hf = __uint_as_float(hb);
                    uint32_t lb = tf32r(v - hf);
                    h[e] = hf;
                    l[e] = __uint_as_float(lb);
                }
                *reinterpret_cast<float4*>(dsth[s]) = hv;
                *reinterpret_cast<float4*>(dstl[s]) = lv;
            }
        }
        __syncthreads();
        if (kt + 1 < C / KT) LOADK((kt + 1) * KT);

#pragma unroll
        for (int k8 = 0; k8 < 16; k8 += 8) {
            const int kr0 = (k8 + kq) * SP;
            const int kr4 = (k8 + kq + 4) * SP;
            uint32_t ah[4][4], al[4][4], bh[4][2], bl[4][2];
#pragma unroll
            for (int mf = 0; mf < 4; mf++) {
                int base = wi + mf * 16 + rr;
                ah[mf][0] = __float_as_uint(Ah[kr0 + base]);
                ah[mf][1] = __float_as_uint(Ah[kr0 + base + 8]);
                ah[mf][2] = __float_as_uint(Ah[kr4 + base]);
                ah[mf][3] = __float_as_uint(Ah[kr4 + base + 8]);
                al[mf][0] = __float_as_uint(Al[kr0 + base]);
                al[mf][1] = __float_as_uint(Al[kr0 + base + 8]);
                al[mf][2] = __float_as_uint(Al[kr4 + base]);
                al[mf][3] = __float_as_uint(Al[kr4 + base + 8]);
            }
#pragma unroll
            for (int nf = 0; nf < 4; nf++) {
                int nb = wj + nf * 8 + rr;
                bh[nf][0] = __float_as_uint(Bh[kr0 + nb]);
                bh[nf][1] = __float_as_uint(Bh[kr4 + nb]);
                bl[nf][0] = __float_as_uint(Bl[kr0 + nb]);
                bl[nf][1] = __float_as_uint(Bl[kr4 + nb]);
            }
#pragma unroll
            for (int mf = 0; mf < 4; mf++)
#pragma unroll
                for (int nf = 0; nf < 4; nf++) {
                    mma8(D[mf][nf], ah[mf], bl[nf]);
                    mma8(D[mf][nf], al[mf], bh[nf]);
                    mma8(D[mf][nf], ah[mf], bh[nf]);
                }
        }
    }
#undef LOADK

    // ---------------- epilogue: 4 chunks of 32 i-rows ----------------
    const size_t bN = (size_t)b * N;
    float tmax = 0.f;

    for (int g = 0; g < 4; g++) {
        __syncthreads();   // staging smem free
        if (wr == (g >> 1)) {
            int mbase = (g & 1) * 2;
#pragma unroll
            for (int mm = 0; mm < 2; mm++) {
                int mf = mbase + mm;
                int lr = mm * 16 + rr;
#pragma unroll
                for (int nf = 0; nf < 4; nf++) {
                    int cb = wj + nf * 8 + 2 * kq;
                    float d0 = D[mf][nf][0], d1 = D[mf][nf][1];
                    float d2v = D[mf][nf][2], d3 = D[mf][nf][3];
                    Cs[lr * PC + cb] = d0;           Cs[lr * PC + cb + 1] = d1;
                    Cs[(lr + 8) * PC + cb] = d2v;    Cs[(lr + 8) * PC + cb + 1] = d3;
                    Cst[cb * PT + lr] = d0;          Cst[(cb + 1) * PT + lr] = d1;
                    Cst[cb * PT + lr + 8] = d2v;     Cst[(cb + 1) * PT + lr + 8] = d3;
                }
            }
        }
        __syncthreads();

        // straight write: rows i0+g*32..+31, cols j0..j0+127
#pragma unroll
        for (int w2 = 0; w2 < 4; w2++) {
            int slot = tid + 256 * w2;     // 1024 slots
            int jr = slot >> 5;
            int q4 = slot & 31;
            int gi = i0 + g * 32 + jr;
            int gj = j0 + q4 * 4;
            if (gi < N && gj < N) {
                float sqi_v = SQ[gi];
                float4 v = *reinterpret_cast<float4*>(&Cs[jr * PC + q4 * 4]);
                float4 o;
                o.x = fmaxf(sqi_v + SQ[gj + 0] - 2.f * v.x, 0.f);
                o.y = fmaxf(sqi_v + SQ[gj + 1] - 2.f * v.y, 0.f);
                o.z = fmaxf(sqi_v + SQ[gj + 2] - 2.f * v.z, 0.f);
                o.w = fmaxf(sqi_v + SQ[gj + 3] - 2.f * v.w, 0.f);
                tmax = fmaxf(tmax, fmaxf(fmaxf(o.x, o.y), fmaxf(o.z, o.w)));
                *reinterpret_cast<float4*>(&g_d2[(bN + gi) * N + gj]) = o;
            }
        }

        // mirror write: rows j0..j0+127, cols i0+g*32..+31
        if (ti != tj) {
#pragma unroll
            for (int w2 = 0; w2 < 4; w2++) {
                int slot = tid + 256 * w2;   // 1024 slots = 128 rows x 8 float4
                int jr2 = slot >> 3;
                int q42 = slot & 7;
                int gj = j0 + jr2;
                int gi = i0 + g * 32 + q42 * 4;
                if (gj < N && gi < N) {
                    float sqj_v = SQ[gj];
                    float4 v = *reinterpret_cast<float4*>(&Cst[jr2 * PT + q42 * 4]);
                    float4 o;
                    o.x = fmaxf(SQ[gi + 0] + sqj_v - 2.f * v.x, 0.f);
                    o.y = fmaxf(SQ[gi + 1] + sqj_v - 2.f * v.y, 0.f);
                    o.z = fmaxf(SQ[gi + 2] + sqj_v - 2.f * v.z, 0.f);
                    o.w = fmaxf(SQ[gi + 3] + sqj_v - 2.f * v.w, 0.f);
                    *reinterpret_cast<float4*>(&g_d2[(bN + gj) * N + gi]) = o;
                }
            }
        }
    }

    // block max -> one atomic per block
    red[tid] = tmax;
    __syncthreads();
    for (int o = 128; o > 0; o >>= 1) {
        if (tid < o) red[tid] = fmaxf(red[tid], red[tid + o]);
        __syncthreads();
    }
    if (tid == 0) atomicMax(&g_maxb[b], __float_as_uint(red[0]));
}

// branchless sorted-5 insert: keeps b0<=b1<=b2<=b3<=b4 = 5 smallest
#define INS5(v) {                                   \
        float w_ = (v), t_;                         \
        t_ = fminf(b0, w_); w_ = fmaxf(b0, w_); b0 = t_; \
        t_ = fminf(b1, w_); w_ = fmaxf(b1, w_); b1 = t_; \
        t_ = fminf(b2, w_); w_ = fmaxf(b2, w_); b2 = t_; \
        t_ = fminf(b3, w_); w_ = fmaxf(b3, w_); b3 = t_; \
        b4 = fminf(b4, w_);                         \
    }

// 5-NN density + threefry noise — one WARP per row, branchless insert
__global__ void knn_kernel() {
    int w = (blockIdx.x * blockDim.x + threadIdx.x) >> 5;
    int lane = threadIdx.x & 31;
    if (w >= B * N) return;
    const float4* row = reinterpret_cast<const float4*>(&g_d2[(size_t)w * N]);
    float b0 = 3.4e38f, b1 = 3.4e38f, b2 = 3.4e38f, b3 = 3.4e38f, b4 = 3.4e38f;
#pragma unroll 4
    for (int q = lane; q < NQ; q += 32) {
        float4 v = row[q];
        INS5(v.x); INS5(v.y); INS5(v.z); INS5(v.w);
    }
    float s = 0.f;
#pragma unroll
    for (int t = 0; t < 5; t++) {
        float m = b0;
#pragma unroll
        for (int o = 16; o > 0; o >>= 1) m = fminf(m, __shfl_xor_sync(0xffffffffu, m, o));
        unsigned bal = __ballot_sync(0xffffffffu, b0 == m);
        if (lane == (__ffs(bal) - 1)) {
            b0 = b1; b1 = b2; b2 = b3; b3 = b4; b4 = 3.4e38f;
        }
        float d = sqrtf(m) / 16.0f;
        s = s + d * d;
    }
    if (lane == 0)
        g_dens[w] = expf(-(s / 5.0f)) + jax_uniform_noise(w) * 1e-6f;
}

// dist_parent + score — one WARP per row (coalesced)
__global__ void parent_kernel() {
    int w = (blockIdx.x * blockDim.x + threadIdx.x) >> 5;
    int lane = threadIdx.x & 31;
    if (w >= B * N) return;
    int b = w / N;
    float di = g_dens[w];
    const float4* row = reinterpret_cast<const float4*>(&g_d2[(size_t)w * N]);
    const float4* dr  = reinterpret_cast<const float4*>(&g_dens[(size_t)b * N]);
    float mn = 3.4e38f;
#pragma unroll 4
    for (int q = lane; q < NQ; q += 32) {
        float4 v = row[q];
        float4 dd = dr[q];
        if (dd.x > di) mn = fminf(mn, v.x);
        if (dd.y > di) mn = fminf(mn, v.y);
        if (dd.z > di) mn = fminf(mn, v.z);
        if (dd.w > di) mn = fminf(mn, v.w);
    }
#pragma unroll
    for (int o = 16; o > 0; o >>= 1) mn = fminf(mn, __shfl_xor_sync(0xffffffffu, mn, o));
    if (lane == 0) {
        float dmax = sqrtf(__uint_as_float(g_maxb[b])) / 16.0f;
        float dp = fminf(dmax, sqrtf(mn) / 16.0f);
        g_score[w] = dp * di;
    }
}

// per-batch top-50, jax top_k tie-break (lower index wins on equal score)
__global__ void topk_kernel() {
    int b = blockIdx.x;
    __shared__ float s[N];
    __shared__ float rs[256];
    __shared__ int   ri[256];
    int t = threadIdx.x;
    for (int i = t; i < N; i += 256) s[i] = g_score[b * N + i];
    __syncthreads();
    for (int m = 0; m < NC; m++) {
        float bs = -3.4e38f;
        int   bi = N;
        for (int i = t; i < N; i += 256) {
            float v = s[i];
            if (v > bs || (v == bs && i < bi)) { bs = v; bi = i; }
        }
        rs[t] = bs; ri[t] = bi;
        __syncthreads();
        for (int o = 128; o > 0; o >>= 1) {
            if (t < o) {
                if (rs[t + o] > rs[t] || (rs[t + o] == rs[t] && ri[t + o] < ri[t])) {
                    rs[t] = rs[t + o]; ri[t] = ri[t + o];
                }
            }
            __syncthreads();
        }
        if (t == 0) {
            g_idx[b * NC + m] = ri[0];
            s[ri[0]] = -3.4e38f;
        }
        __syncthreads();
    }
}

__global__ void gather_kernel(const float* __restrict__ x, float* __restrict__ out) {
    int g = blockIdx.x * blockDim.x + threadIdx.x;
    if (g >= B * C * NC) return;
    int m = g % NC;
    int c = (g / NC) % C;
    int b = g / (NC * C);
    int idx = g_idx[b * NC + m];
    out[g] = x[(size_t)b * C * N + (size_t)c * N + idx];
}

// ---------------- launch -----------------------------------------------------
extern "C" void kernel_launch(void* const* d_in, const int* in_sizes, int n_in,
                              void* d_out, int out_size) {
    const float* x = (const float*)d_in[0];
    float* out = (float*)d_out;

    init_kernel<<<1, 32>>>();
    sq_kernel<<<(B * N + 255) / 256, 256>>>(x);
    dim3 gg(NPAIRS, 1, B);
    gram_kernel<<<gg, 256>>>(x);
    int rows = B * N;
    knn_kernel<<<(rows * 32 + 255) / 256, 256>>>();
    parent_kernel<<<(rows * 32 + 255) / 256, 256>>>();
    topk_kernel<<<B, 256>>>();
    gather_kernel<<<(B * C * NC + 255) / 256, 256>>>(x, out);
}

// round 7
// speedup vs baseline: 1.0749x; 1.0749x over previous
#include <cuda_runtime.h>
#include <cstdint>

#define B 8
#define C 256
#define N 3136
#define NP 3200
#define NQ (N/4)
#define NC 50
#define TILE 128
#define NT 25
#define NPAIRS (NT*(NT+1)/2)
#define ASEGS 200              // NP/16
#define BSEGS 400              // NP/8
#define BUF_FLOATS 8192
#define DSMEM_BYTES (2*BUF_FLOATS*4)   // 65536
#define PC 132
#define PT 36

// ---------------- scratch (static device globals: allocation-guard safe) ----
__device__ float g_d2[(size_t)B * N * N];
__device__ __align__(16) float g_ah[(size_t)B * ASEGS * 32 * 128];
__device__ __align__(16) float g_al[(size_t)B * ASEGS * 32 * 128];
__device__ __align__(16) float g_bh[(size_t)B * BSEGS * 32 * 64];
__device__ __align__(16) float g_bl[(size_t)B * BSEGS * 32 * 64];
__device__ float    g_sq[B * N];
__device__ float    g_dens[B * N];
__device__ float    g_score[B * N];
__device__ unsigned g_maxb[B];
__device__ int      g_idx[B * NC];

// ---------------- threefry-2x32 (JAX-compatible) ---------------------------
__device__ __forceinline__ uint32_t rotl32(uint32_t x, int r) {
    return (x << r) | (x >> (32 - r));
}

__device__ __forceinline__ void threefry2x32_k42(uint32_t x0, uint32_t x1,
                                                 uint32_t& o0, uint32_t& o1) {
    const uint32_t ks0 = 0u;
    const uint32_t ks1 = 42u;
    const uint32_t ks2 = 0x1BD11BDAu ^ 42u;
    x0 += ks0; x1 += ks1;
#define TF_RND(r) { x0 += x1; x1 = rotl32(x1, r); x1 ^= x0; }
    TF_RND(13) TF_RND(15) TF_RND(26) TF_RND(6)
    x0 += ks1; x1 += ks2 + 1u;
    TF_RND(17) TF_RND(29) TF_RND(16) TF_RND(24)
    x0 += ks2; x1 += ks0 + 2u;
    TF_RND(13) TF_RND(15) TF_RND(26) TF_RND(6)
    x0 += ks0; x1 += ks1 + 3u;
    TF_RND(17) TF_RND(29) TF_RND(16) TF_RND(24)
    x0 += ks1; x1 += ks2 + 4u;
    TF_RND(13) TF_RND(15) TF_RND(26) TF_RND(6)
    x0 += ks2; x1 += ks0 + 5u;
#undef TF_RND
    o0 = x0; o1 = x1;
}

__device__ __forceinline__ float jax_uniform_noise(int g) {
    const int half = (B * N) / 2;  // 12544
    uint32_t lane = (g < half) ? (uint32_t)g : (uint32_t)(g - half);
    uint32_t o0, o1;
    threefry2x32_k42(lane, lane + (uint32_t)half, o0, o1);
    uint32_t bits = (g < half) ? o0 : o1;
    return __uint_as_float((bits >> 9) | 0x3F800000u) - 1.0f;
}

// ---------------- tf32 helpers ----------------------------------------------
__device__ __forceinline__ uint32_t tf32r(float x) {
    uint32_t y;
    asm("cvt.rna.tf32.f32 %0, %1;" : "=r"(y) : "f"(x));
    return y;
}

__device__ __forceinline__ void split1(float v, float& h, float& l) {
    float hf = __uint_as_float(tf32r(v));
    h = hf;
    l = __uint_as_float(tf32r(v - hf));
}

__device__ __forceinline__ void mma8(float d[4], const uint32_t a[4], const uint32_t b[2]) {
    asm volatile(
        "mma.sync.aligned.m16n8k8.row.col.f32.tf32.tf32.f32 "
        "{%0,%1,%2,%3}, {%4,%5,%6,%7}, {%8,%9}, {%0,%1,%2,%3};"
        : "+f"(d[0]), "+f"(d[1]), "+f"(d[2]), "+f"(d[3])
        : "r"(a[0]), "r"(a[1]), "r"(a[2]), "r"(a[3]), "r"(b[0]), "r"(b[1]));
}

__device__ __forceinline__ uint32_t smem_u32(const void* p) {
    uint32_t a;
    asm("{ .reg .u64 t; cvta.to.shared.u64 t, %1; cvt.u32.u64 %0, t; }"
        : "=r"(a) : "l"(p));
    return a;
}

__device__ __forceinline__ void cp16(uint32_t d, const float* s) {
    asm volatile("cp.async.cg.shared.global [%0], [%1], 16;" :: "r"(d), "l"(s));
}

// ---------------- kernels ---------------------------------------------------
__global__ void init_kernel() {
    int t = threadIdx.x;
    if (t < B) g_maxb[t] = 0u;
}

__global__ void sq_kernel(const float* __restrict__ x) {
    int g = blockIdx.x * blockDim.x + threadIdx.x;
    if (g >= B * N) return;
    int b = g / N, n = g % N;
    const float* p = x + (size_t)b * C * N + n;
    float s = 0.f;
#pragma unroll 8
    for (int c = 0; c < C; c++) {
        float v = p[(size_t)c * N];
        s = fmaf(v, v, s);
    }
    g_sq[g] = s;
}

// transpose + tf32 hi/lo split into GLOBAL FRAGMENT LAYOUTS (A-role + B-role)
__global__ void split_kernel(const float* __restrict__ x) {
    const int seg = blockIdx.x;     // 16-row segment (0..199)
    const int b = blockIdx.y;
    const int row0 = seg * 16;
    __shared__ float sv[16][260];
    const int t = threadIdx.x;
#pragma unroll
    for (int i = 0; i < 16; i++) {
        int r = t & 15;
        int k = (t >> 4) + i * 16;
        int row = row0 + r;
        float v = (row < N) ? x[((size_t)b * C + k) * N + row] : 0.f;
        sv[r][k] = v;
    }
    __syncthreads();
    // A-role: [seg][k8][lane][reg0..3], reg = a0..a3 of m16n8k8 row-major A
#pragma unroll
    for (int j = 0; j < 4; j++) {
        int u = t + j * 256;
        int k8 = u >> 5, lane = u & 31;
        int rl = lane >> 2, tg = lane & 3;
        int k = k8 * 8 + tg;
        float4 hv, lv;
        split1(sv[rl][k],         hv.x, lv.x);
        split1(sv[rl + 8][k],     hv.y, lv.y);
        split1(sv[rl][k + 4],     hv.z, lv.z);
        split1(sv[rl + 8][k + 4], hv.w, lv.w);
        size_t base = (((size_t)b * ASEGS + seg) * 32 + k8) * 128 + lane * 4;
        *reinterpret_cast<float4*>(&g_ah[base]) = hv;
        *reinterpret_cast<float4*>(&g_al[base]) = lv;
    }
    // B-role: [colseg][k8][lane][reg0..1], reg = b0..b1 of m16n8k8 col-major B
#pragma unroll
    for (int j = 0; j < 8; j++) {
        int u = t + j * 256;
        int cs = u >> 10, rem = u & 1023;
        int k8 = rem >> 5, lane = rem & 31;
        int col = cs * 8 + (lane >> 2), tg = lane & 3;
        int k = k8 * 8 + tg;
        float2 hv, lv;
        split1(sv[col][k],     hv.x, lv.x);
        split1(sv[col][k + 4], hv.y, lv.y);
        size_t base = (((size_t)b * BSEGS + seg * 2 + cs) * 32 + k8) * 64 + lane * 2;
        *reinterpret_cast<float2*>(&g_bh[base]) = hv;
        *reinterpret_cast<float2*>(&g_bl[base]) = lv;
    }
}

// Symmetric Gram via tf32x3 mma.sync; cp.async double-buffered identity-copy
// staging; conflict-free vector frag loads. 128x128 tile, 8 warps (64x32 each).
__global__ __launch_bounds__(256, 2) void gram_kernel() {
    extern __shared__ float dyn[];
    __shared__ float red[256];

    const int b = blockIdx.z;
    int rem = blockIdx.x;
    int ti = 0;
    while (rem >= NT - ti) { rem -= NT - ti; ti++; }
    const int tj = ti + rem;
    const int i0 = ti * TILE, j0 = tj * TILE;

    const int tid = threadIdx.x, lane = tid & 31, wid = tid >> 5;
    const int wr = wid >> 2, wc = wid & 3;
    const int kq = lane & 3, rr = lane >> 2;
    const uint32_t smb = smem_u32(dyn);

    // cp.async plumbing: each thread copies 2 x 16B per region per k16
    const int u0 = tid * 2, u1 = u0 + 1;
    const float* Abase_h = g_ah + ((size_t)b * ASEGS + ti * 8) * 4096;
    const float* Abase_l = g_al + ((size_t)b * ASEGS + ti * 8) * 4096;
    const float* Bbase_h = g_bh + ((size_t)b * BSEGS + tj * 16) * 2048;
    const float* Bbase_l = g_bl + ((size_t)b * BSEGS + tj * 16) * 2048;
    const int a0 = ((u0 >> 5) & 7) * 4096 + (u0 >> 8) * 128 + (u0 & 31) * 4;
    const int a1 = ((u1 >> 5) & 7) * 4096 + (u1 >> 8) * 128 + (u1 & 31) * 4;
    const int bo0 = ((u0 >> 4) & 15) * 2048 + (u0 >> 8) * 64 + (u0 & 15) * 4;
    const int bo1 = ((u1 >> 4) & 15) * 2048 + (u1 >> 8) * 64 + (u1 & 15) * 4;
    const uint32_t d0 = smb + u0 * 16, d1 = smb + u1 * 16;

#define ISSUE(kc, buf) {                                              \
        uint32_t bo = (buf) * 32768u;                                 \
        cp16(d0 + bo,          Abase_h + a0 + (kc) * 256);            \
        cp16(d1 + bo,          Abase_h + a1 + (kc) * 256);            \
        cp16(d0 + bo + 8192,   Abase_l + a0 + (kc) * 256);            \
        cp16(d1 + bo + 8192,   Abase_l + a1 + (kc) * 256);            \
        cp16(d0 + bo + 16384,  Bbase_h + bo0 + (kc) * 128);           \
        cp16(d1 + bo + 16384,  Bbase_h + bo1 + (kc) * 128);           \
        cp16(d0 + bo + 24576,  Bbase_l + bo0 + (kc) * 128);           \
        cp16(d1 + bo + 24576,  Bbase_l + bo1 + (kc) * 128);           \
        asm volatile("cp.async.commit_group;");                       \
    }

    float D[4][4][4];
#pragma unroll
    for (int mf = 0; mf < 4; mf++)
#pragma unroll
        for (int nf = 0; nf < 4; nf++)
#pragma unroll
            for (int e = 0; e < 4; e++) D[mf][nf][e] = 0.f;

    ISSUE(0, 0);
#pragma unroll 1
    for (int kc = 0; kc < 16; kc++) {
        if (kc + 1 < 16) {
            ISSUE(kc + 1, (kc + 1) & 1);
            asm volatile("cp.async.wait_group 1;");
        } else {
            asm volatile("cp.async.wait_group 0;");
        }
        __syncthreads();
        const float* bb = dyn + (kc & 1) * BUF_FLOATS;
#pragma unroll
        for (int k8 = 0; k8 < 2; k8++) {
            uint32_t ah[4][4], al[4][4], bh[4][2], bl[4][2];
#pragma unroll
            for (int mf = 0; mf < 4; mf++) {
                int off = (k8 * 8 + wr * 4 + mf) * 128 + lane * 4;
                float4 h = *reinterpret_cast<const float4*>(&bb[off]);
                float4 l = *reinterpret_cast<const float4*>(&bb[2048 + off]);
                ah[mf][0] = __float_as_uint(h.x); ah[mf][1] = __float_as_uint(h.y);
                ah[mf][2] = __float_as_uint(h.z); ah[mf][3] = __float_as_uint(h.w);
                al[mf][0] = __float_as_uint(l.x); al[mf][1] = __float_as_uint(l.y);
                al[mf][2] = __float_as_uint(l.z); al[mf][3] = __float_as_uint(l.w);
            }
#pragma unroll
            for (int nf = 0; nf < 4; nf++) {
                int off = (k8 * 16 + wc * 4 + nf) * 64 + lane * 2;
                float2 h = *reinterpret_cast<const float2*>(&bb[4096 + off]);
                float2 l = *reinterpret_cast<const float2*>(&bb[6144 + off]);
                bh[nf][0] = __float_as_uint(h.x); bh[nf][1] = __float_as_uint(h.y);
                bl[nf][0] = __float_as_uint(l.x); bl[nf][1] = __float_as_uint(l.y);
            }
#pragma unroll
            for (int mf = 0; mf < 4; mf++)
#pragma unroll
                for (int nf = 0; nf < 4; nf++) {
                    mma8(D[mf][nf], ah[mf], bl[nf]);
                    mma8(D[mf][nf], al[mf], bh[nf]);
                    mma8(D[mf][nf], ah[mf], bh[nf]);
                }
        }
        __syncthreads();
    }
#undef ISSUE

    // ---------------- epilogue: 4 chunks of 32 i-rows (R5-verified) ----------
    const float* SQ = &g_sq[b * N];
    const size_t bN = (size_t)b * N;
    float* Cs = dyn;
    float* Cst = dyn + 32 * PC;
    float tmax = 0.f;

    for (int g5 = 0; g5 < 4; g5++) {
        __syncthreads();
        if (wr == (g5 >> 1)) {
            int mbase = (g5 & 1) * 2;
#pragma unroll
            for (int mm = 0; mm < 2; mm++) {
                int mf = mbase + mm;
                int lr = mm * 16 + rr;
#pragma unroll
                for (int nf = 0; nf < 4; nf++) {
                    int cb = wc * 32 + nf * 8 + 2 * kq;
                    float e0 = D[mf][nf][0], e1 = D[mf][nf][1];
                    float e2 = D[mf][nf][2], e3 = D[mf][nf][3];
                    Cs[lr * PC + cb] = e0;          Cs[lr * PC + cb + 1] = e1;
                    Cs[(lr + 8) * PC + cb] = e2;    Cs[(lr + 8) * PC + cb + 1] = e3;
                    Cst[cb * PT + lr] = e0;         Cst[(cb + 1) * PT + lr] = e1;
                    Cst[cb * PT + lr + 8] = e2;     Cst[(cb + 1) * PT + lr + 8] = e3;
                }
            }
        }
        __syncthreads();

#pragma unroll
        for (int w2 = 0; w2 < 4; w2++) {
            int slot = tid + 256 * w2;
            int jr = slot >> 5, q4 = slot & 31;
            int gi = i0 + g5 * 32 + jr, gj = j0 + q4 * 4;
            if (gi < N && gj < N) {
                float sqi = SQ[gi];
                float4 v = *reinterpret_cast<float4*>(&Cs[jr * PC + q4 * 4]);
                float4 o;
                o.x = fmaxf(sqi + SQ[gj + 0] - 2.f * v.x, 0.f);
                o.y = fmaxf(sqi + SQ[gj + 1] - 2.f * v.y, 0.f);
                o.z = fmaxf(sqi + SQ[gj + 2] - 2.f * v.z, 0.f);
                o.w = fmaxf(sqi + SQ[gj + 3] - 2.f * v.w, 0.f);
                tmax = fmaxf(tmax, fmaxf(fmaxf(o.x, o.y), fmaxf(o.z, o.w)));
                *reinterpret_cast<float4*>(&g_d2[(bN + gi) * N + gj]) = o;
            }
        }
        if (ti != tj) {
#pragma unroll
            for (int w2 = 0; w2 < 4; w2++) {
                int slot = tid + 256 * w2;
                int jr2 = slot >> 3, q42 = slot & 7;
                int gj = j0 + jr2, gi = i0 + g5 * 32 + q42 * 4;
                if (gj < N && gi < N) {
                    float sqj = SQ[gj];
                    float4 v = *reinterpret_cast<float4*>(&Cst[jr2 * PT + q42 * 4]);
                    float4 o;
                    o.x = fmaxf(SQ[gi + 0] + sqj - 2.f * v.x, 0.f);
                    o.y = fmaxf(SQ[gi + 1] + sqj - 2.f * v.y, 0.f);
                    o.z = fmaxf(SQ[gi + 2] + sqj - 2.f * v.z, 0.f);
                    o.w = fmaxf(SQ[gi + 3] + sqj - 2.f * v.w, 0.f);
                    *reinterpret_cast<float4*>(&g_d2[(bN + gj) * N + gi]) = o;
                }
            }
        }
    }

    red[tid] = tmax;
    __syncthreads();
    for (int o = 128; o > 0; o >>= 1) {
        if (tid < o) red[tid] = fmaxf(red[tid], red[tid + o]);
        __syncthreads();
    }
    if (tid == 0) atomicMax(&g_maxb[b], __float_as_uint(red[0]));
}

// branchless sorted-5 insert
#define INS5(v) {                                   \
        float w_ = (v), t_;                         \
        t_ = fminf(b0, w_); w_ = fmaxf(b0, w_); b0 = t_; \
        t_ = fminf(b1, w_); w_ = fmaxf(b1, w_); b1 = t_; \
        t_ = fminf(b2, w_); w_ = fmaxf(b2, w_); b2 = t_; \
        t_ = fminf(b3, w_); w_ = fmaxf(b3, w_); b3 = t_; \
        b4 = fminf(b4, w_);                         \
    }

__global__ void knn_kernel() {
    int w = (blockIdx.x * blockDim.x + threadIdx.x) >> 5;
    int lane = threadIdx.x & 31;
    if (w >= B * N) return;
    const float4* row = reinterpret_cast<const float4*>(&g_d2[(size_t)w * N]);
    float b0 = 3.4e38f, b1 = 3.4e38f, b2 = 3.4e38f, b3 = 3.4e38f, b4 = 3.4e38f;
#pragma unroll 4
    for (int q = lane; q < NQ; q += 32) {
        float4 v = row[q];
        INS5(v.x); INS5(v.y); INS5(v.z); INS5(v.w);
    }
    float s = 0.f;
#pragma unroll
    for (int t = 0; t < 5; t++) {
        float m = b0;
#pragma unroll
        for (int o = 16; o > 0; o >>= 1) m = fminf(m, __shfl_xor_sync(0xffffffffu, m, o));
        unsigned bal = __ballot_sync(0xffffffffu, b0 == m);
        if (lane == (__ffs(bal) - 1)) {
            b0 = b1; b1 = b2; b2 = b3; b3 = b4; b4 = 3.4e38f;
        }
        float d = sqrtf(m) / 16.0f;
        s = s + d * d;
    }
    if (lane == 0)
        g_dens[w] = expf(-(s / 5.0f)) + jax_uniform_noise(w) * 1e-6f;
}

__global__ void parent_kernel() {
    int w = (blockIdx.x * blockDim.x + threadIdx.x) >> 5;
    int lane = threadIdx.x & 31;
    if (w >= B * N) return;
    int b = w / N;
    float di = g_dens[w];
    const float4* row = reinterpret_cast<const float4*>(&g_d2[(size_t)w * N]);
    const float4* dr  = reinterpret_cast<const float4*>(&g_dens[(size_t)b * N]);
    float mn = 3.4e38f;
#pragma unroll 4
    for (int q = lane; q < NQ; q += 32) {
        float4 v = row[q];
        float4 dd = dr[q];
        if (dd.x > di) mn = fminf(mn, v.x);
        if (dd.y > di) mn = fminf(mn, v.y);
        if (dd.z > di) mn = fminf(mn, v.z);
        if (dd.w > di) mn = fminf(mn, v.w);
    }
#pragma unroll
    for (int o = 16; o > 0; o >>= 1) mn = fminf(mn, __shfl_xor_sync(0xffffffffu, mn, o));
    if (lane == 0) {
        float dmax = sqrtf(__uint_as_float(g_maxb[b])) / 16.0f;
        float dp = fminf(dmax, sqrtf(mn) / 16.0f);
        g_score[w] = dp * di;
    }
}

// per-batch top-50 with warp-shuffle reductions (lower index wins ties)
__global__ void topk_kernel() {
    int b = blockIdx.x;
    __shared__ float s[N];
    __shared__ float wv[32];
    __shared__ int   wix[32];
    int t = threadIdx.x, lane = t & 31, w = t >> 5;
    for (int i = t; i < N; i += 1024) s[i] = g_score[b * N + i];
    __syncthreads();
    for (int m = 0; m < NC; m++) {
        float bs = -3.4e38f;
        int   bi = N;
        for (int i = t; i < N; i += 1024) {
            float v = s[i];
            if (v > bs) { bs = v; bi = i; }
        }
#pragma unroll
        for (int o = 16; o > 0; o >>= 1) {
            float ov = __shfl_xor_sync(0xffffffffu, bs, o);
            int   oi = __shfl_xor_sync(0xffffffffu, bi, o);
            if (ov > bs || (ov == bs && oi < bi)) { bs = ov; bi = oi; }
        }
        if (lane == 0) { wv[w] = bs; wix[w] = bi; }
        __syncthreads();
        if (w == 0) {
            bs = wv[lane]; bi = wix[lane];
#pragma unroll
            for (int o = 16; o > 0; o >>= 1) {
                float ov = __shfl_xor_sync(0xffffffffu, bs, o);
                int   oi = __shfl_xor_sync(0xffffffffu, bi, o);
                if (ov > bs || (ov == bs && oi < bi)) { bs = ov; bi = oi; }
            }
            if (lane == 0) { g_idx[b * NC + m] = bi; s[bi] = -3.4e38f; }
        }
        __syncthreads();
    }
}

__global__ void gather_kernel(const float* __restrict__ x, float* __restrict__ out) {
    int g = blockIdx.x * blockDim.x + threadIdx.x;
    if (g >= B * C * NC) return;
    int m = g % NC;
    int c = (g / NC) % C;
    int b = g / (NC * C);
    int idx = g_idx[b * NC + m];
    out[g] = x[(size_t)b * C * N + (size_t)c * N + idx];
}

// ---------------- launch -----------------------------------------------------
extern "C" void kernel_launch(void* const* d_in, const int* in_sizes, int n_in,
                              void* d_out, int out_size) {
    const float* x = (const float*)d_in[0];
    float* out = (float*)d_out;

    cudaFuncSetAttribute(gram_kernel,
                         cudaFuncAttributeMaxDynamicSharedMemorySize, DSMEM_BYTES);

    init_kernel<<<1, 32>>>();
    sq_kernel<<<(B * N + 255) / 256, 256>>>(x);
    dim3 sg(ASEGS, B);
    split_kernel<<<sg, 256>>>(x);
    dim3 gg(NPAIRS, 1, B);
    gram_kernel<<<gg, 256, DSMEM_BYTES>>>();
    int rows = B * N;
    knn_kernel<<<(rows * 32 + 255) / 256, 256>>>();
    parent_kernel<<<(rows * 32 + 255) / 256, 256>>>();
    topk_kernel<<<B, 1024>>>();
    gather_kernel<<<(B * C * NC + 255) / 256, 256>>>(x, out);
}

// round 8
// speedup vs baseline: 1.0773x; 1.0023x over previous
#include <cuda_runtime.h>
#include <cstdint>

#define B 8
#define C 256
#define N 3136
#define NP 3200
#define NQ (N/4)
#define NC 50
#define TILE 128
#define NT 25
#define NPAIRS (NT*(NT+1)/2)
#define ASEGS 200              // NP/16
#define BSEGS 400              // NP/8
#define PC 132
#define PT 36

// ---------------- scratch (static device globals: allocation-guard safe) ----
__device__ float g_d2[(size_t)B * N * N];
__device__ __align__(16) float g_ah[(size_t)B * ASEGS * 32 * 128];
__device__ __align__(16) float g_al[(size_t)B * ASEGS * 32 * 128];
__device__ __align__(16) float g_bh[(size_t)B * BSEGS * 32 * 64];
__device__ __align__(16) float g_bl[(size_t)B * BSEGS * 32 * 64];
__device__ float    g_sq[B * N];
__device__ float    g_dens[B * N];
__device__ float    g_score[B * N];
__device__ unsigned g_maxb[B];
__device__ int      g_idx[B * NC];

// ---------------- threefry-2x32 (JAX-compatible) ---------------------------
__device__ __forceinline__ uint32_t rotl32(uint32_t x, int r) {
    return (x << r) | (x >> (32 - r));
}

__device__ __forceinline__ void threefry2x32_k42(uint32_t x0, uint32_t x1,
                                                 uint32_t& o0, uint32_t& o1) {
    const uint32_t ks0 = 0u;
    const uint32_t ks1 = 42u;
    const uint32_t ks2 = 0x1BD11BDAu ^ 42u;
    x0 += ks0; x1 += ks1;
#define TF_RND(r) { x0 += x1; x1 = rotl32(x1, r); x1 ^= x0; }
    TF_RND(13) TF_RND(15) TF_RND(26) TF_RND(6)
    x0 += ks1; x1 += ks2 + 1u;
    TF_RND(17) TF_RND(29) TF_RND(16) TF_RND(24)
    x0 += ks2; x1 += ks0 + 2u;
    TF_RND(13) TF_RND(15) TF_RND(26) TF_RND(6)
    x0 += ks0; x1 += ks1 + 3u;
    TF_RND(17) TF_RND(29) TF_RND(16) TF_RND(24)
    x0 += ks1; x1 += ks2 + 4u;
    TF_RND(13) TF_RND(15) TF_RND(26) TF_RND(6)
    x0 += ks2; x1 += ks0 + 5u;
#undef TF_RND
    o0 = x0; o1 = x1;
}

__device__ __forceinline__ float jax_uniform_noise(int g) {
    const int half = (B * N) / 2;  // 12544
    uint32_t lane = (g < half) ? (uint32_t)g : (uint32_t)(g - half);
    uint32_t o0, o1;
    threefry2x32_k42(lane, lane + (uint32_t)half, o0, o1);
    uint32_t bits = (g < half) ? o0 : o1;
    return __uint_as_float((bits >> 9) | 0x3F800000u) - 1.0f;
}

// ---------------- tf32 helpers ----------------------------------------------
__device__ __forceinline__ uint32_t tf32r(float x) {
    uint32_t y;
    asm("cvt.rna.tf32.f32 %0, %1;" : "=r"(y) : "f"(x));
    return y;
}

__device__ __forceinline__ void split1(float v, float& h, float& l) {
    float hf = __uint_as_float(tf32r(v));
    h = hf;
    l = __uint_as_float(tf32r(v - hf));
}

__device__ __forceinline__ void mma8(float d[4], const uint32_t a[4], const uint32_t b[2]) {
    asm volatile(
        "mma.sync.aligned.m16n8k8.row.col.f32.tf32.tf32.f32 "
        "{%0,%1,%2,%3}, {%4,%5,%6,%7}, {%8,%9}, {%0,%1,%2,%3};"
        : "+f"(d[0]), "+f"(d[1]), "+f"(d[2]), "+f"(d[3])
        : "r"(a[0]), "r"(a[1]), "r"(a[2]), "r"(a[3]), "r"(b[0]), "r"(b[1]));
}

// ---------------- kernels ---------------------------------------------------
__global__ void init_kernel() {
    int t = threadIdx.x;
    if (t < B) g_maxb[t] = 0u;
}

__global__ void sq_kernel(const float* __restrict__ x) {
    int g = blockIdx.x * blockDim.x + threadIdx.x;
    if (g >= B * N) return;
    int b = g / N, n = g % N;
    const float* p = x + (size_t)b * C * N + n;
    float s = 0.f;
#pragma unroll 8
    for (int c = 0; c < C; c++) {
        float v = p[(size_t)c * N];
        s = fmaf(v, v, s);
    }
    g_sq[g] = s;
}

// transpose + tf32 hi/lo split into GLOBAL FRAGMENT LAYOUTS (A-role + B-role)
__global__ void split_kernel(const float* __restrict__ x) {
    const int seg = blockIdx.x;     // 16-row segment (0..199)
    const int b = blockIdx.y;
    const int row0 = seg * 16;
    __shared__ float sv[16][260];
    const int t = threadIdx.x;
#pragma unroll
    for (int i = 0; i < 16; i++) {
        int r = t & 15;
        int k = (t >> 4) + i * 16;
        int row = row0 + r;
        float v = (row < N) ? x[((size_t)b * C + k) * N + row] : 0.f;
        sv[r][k] = v;
    }
    __syncthreads();
    // A-role: [seg][k8][lane][reg0..3]
#pragma unroll
    for (int j = 0; j < 4; j++) {
        int u = t + j * 256;
        int k8 = u >> 5, lane = u & 31;
        int rl = lane >> 2, tg = lane & 3;
        int k = k8 * 8 + tg;
        float4 hv, lv;
        split1(sv[rl][k],         hv.x, lv.x);
        split1(sv[rl + 8][k],     hv.y, lv.y);
        split1(sv[rl][k + 4],     hv.z, lv.z);
        split1(sv[rl + 8][k + 4], hv.w, lv.w);
        size_t base = (((size_t)b * ASEGS + seg) * 32 + k8) * 128 + lane * 4;
        *reinterpret_cast<float4*>(&g_ah[base]) = hv;
        *reinterpret_cast<float4*>(&g_al[base]) = lv;
    }
    // B-role: [colseg][k8][lane][reg0..1]
#pragma unroll
    for (int j = 0; j < 8; j++) {
        int u = t + j * 256;
        int cs = u >> 10, rem = u & 1023;
        int k8 = rem >> 5, lane = rem & 31;
        int col = cs * 8 + (lane >> 2), tg = lane & 3;
        int k = k8 * 8 + tg;
        float2 hv, lv;
        split1(sv[col][k],     hv.x, lv.x);
        split1(sv[col][k + 4], hv.y, lv.y);
        size_t base = (((size_t)b * BSEGS + seg * 2 + cs) * 32 + k8) * 64 + lane * 2;
        *reinterpret_cast<float2*>(&g_bh[base]) = hv;
        *reinterpret_cast<float2*>(&g_bl[base]) = lv;
    }
}

// Symmetric Gram via tf32x3 mma.sync; fragments LDG'd DIRECTLY from the global
// fragment layout (no smem staging in the mainloop). 128x128 tile, 8 warps.
__global__ __launch_bounds__(256, 2) void gram_kernel() {
    __shared__ float Cs[32 * PC];
    __shared__ float Cst[128 * PT];
    __shared__ float red[256];

    const int b = blockIdx.z;
    int rem = blockIdx.x;
    int ti = 0;
    while (rem >= NT - ti) { rem -= NT - ti; ti++; }
    const int tj = ti + rem;
    const int i0 = ti * TILE, j0 = tj * TILE;

    const int tid = threadIdx.x, lane = tid & 31, wid = tid >> 5;
    const int wr = wid >> 2, wc = wid & 3;
    const int kq = lane & 3, rr = lane >> 2;

    // fragment pointers (uint4/uint2 units): seg stride = 1024 uint4 / colseg 1024 uint2
    const uint4* pah = reinterpret_cast<const uint4*>(
        g_ah + ((size_t)b * ASEGS + ti * 8 + wr * 4) * 4096) + lane;
    const uint4* pal = reinterpret_cast<const uint4*>(
        g_al + ((size_t)b * ASEGS + ti * 8 + wr * 4) * 4096) + lane;
    const uint2* pbh = reinterpret_cast<const uint2*>(
        g_bh + ((size_t)b * BSEGS + tj * 16 + wc * 4) * 2048) + lane;
    const uint2* pbl = reinterpret_cast<const uint2*>(
        g_bl + ((size_t)b * BSEGS + tj * 16 + wc * 4) * 2048) + lane;

    float D[4][4][4];
#pragma unroll
    for (int mf = 0; mf < 4; mf++)
#pragma unroll
        for (int nf = 0; nf < 4; nf++)
#pragma unroll
            for (int e = 0; e < 4; e++) D[mf][nf][e] = 0.f;

#pragma unroll 2
    for (int k8 = 0; k8 < 32; k8++) {
        uint4 AH[4], AL[4];
        uint2 BH[4], BL[4];
#pragma unroll
        for (int mf = 0; mf < 4; mf++) {
            AH[mf] = pah[mf * 1024];
            AL[mf] = pal[mf * 1024];
        }
#pragma unroll
        for (int nf = 0; nf < 4; nf++) {
            BH[nf] = pbh[nf * 1024];
            BL[nf] = pbl[nf * 1024];
        }
        pah += 32; pal += 32; pbh += 32; pbl += 32;   // next k8

#pragma unroll
        for (int mf = 0; mf < 4; mf++) {
            uint32_t ah[4] = {AH[mf].x, AH[mf].y, AH[mf].z, AH[mf].w};
            uint32_t al[4] = {AL[mf].x, AL[mf].y, AL[mf].z, AL[mf].w};
#pragma unroll
            for (int nf = 0; nf < 4; nf++) {
                uint32_t bh[2] = {BH[nf].x, BH[nf].y};
                uint32_t bl[2] = {BL[nf].x, BL[nf].y};
                mma8(D[mf][nf], ah, bl);
                mma8(D[mf][nf], al, bh);
                mma8(D[mf][nf], ah, bh);
            }
        }
    }

    // ---------------- epilogue: 4 chunks of 32 i-rows (validated in R5/R7) ---
    const float* SQ = &g_sq[b * N];
    const size_t bN = (size_t)b * N;
    float tmax = 0.f;

    for (int g5 = 0; g5 < 4; g5++) {
        __syncthreads();
        if (wr == (g5 >> 1)) {
            int mbase = (g5 & 1) * 2;
#pragma unroll
            for (int mm = 0; mm < 2; mm++) {
                int mf = mbase + mm;
                int lr = mm * 16 + rr;
#pragma unroll
                for (int nf = 0; nf < 4; nf++) {
                    int cb = wc * 32 + nf * 8 + 2 * kq;
                    float e0 = D[mf][nf][0], e1 = D[mf][nf][1];
                    float e2 = D[mf][nf][2], e3 = D[mf][nf][3];
                    Cs[lr * PC + cb] = e0;          Cs[lr * PC + cb + 1] = e1;
                    Cs[(lr + 8) * PC + cb] = e2;    Cs[(lr + 8) * PC + cb + 1] = e3;
                    Cst[cb * PT + lr] = e0;         Cst[(cb + 1) * PT + lr] = e1;
                    Cst[cb * PT + lr + 8] = e2;     Cst[(cb + 1) * PT + lr + 8] = e3;
                }
            }
        }
        __syncthreads();

#pragma unroll
        for (int w2 = 0; w2 < 4; w2++) {
            int slot = tid + 256 * w2;
            int jr = slot >> 5, q4 = slot & 31;
            int gi = i0 + g5 * 32 + jr, gj = j0 + q4 * 4;
            if (gi < N && gj < N) {
                float sqi = SQ[gi];
                float4 v = *reinterpret_cast<float4*>(&Cs[jr * PC + q4 * 4]);
                float4 o;
                o.x = fmaxf(sqi + SQ[gj + 0] - 2.f * v.x, 0.f);
                o.y = fmaxf(sqi + SQ[gj + 1] - 2.f * v.y, 0.f);
                o.z = fmaxf(sqi + SQ[gj + 2] - 2.f * v.z, 0.f);
                o.w = fmaxf(sqi + SQ[gj + 3] - 2.f * v.w, 0.f);
                tmax = fmaxf(tmax, fmaxf(fmaxf(o.x, o.y), fmaxf(o.z, o.w)));
                *reinterpret_cast<float4*>(&g_d2[(bN + gi) * N + gj]) = o;
            }
        }
        if (ti != tj) {
#pragma unroll
            for (int w2 = 0; w2 < 4; w2++) {
                int slot = tid + 256 * w2;
                int jr2 = slot >> 3, q42 = slot & 7;
                int gj = j0 + jr2, gi = i0 + g5 * 32 + q42 * 4;
                if (gj < N && gi < N) {
                    float sqj = SQ[gj];
                    float4 v = *reinterpret_cast<float4*>(&Cst[jr2 * PT + q42 * 4]);
                    float4 o;
                    o.x = fmaxf(SQ[gi + 0] + sqj - 2.f * v.x, 0.f);
                    o.y = fmaxf(SQ[gi + 1] + sqj - 2.f * v.y, 0.f);
                    o.z = fmaxf(SQ[gi + 2] + sqj - 2.f * v.z, 0.f);
                    o.w = fmaxf(SQ[gi + 3] + sqj - 2.f * v.w, 0.f);
                    *reinterpret_cast<float4*>(&g_d2[(bN + gj) * N + gi]) = o;
                }
            }
        }
    }

    red[tid] = tmax;
    __syncthreads();
    for (int o = 128; o > 0; o >>= 1) {
        if (tid < o) red[tid] = fmaxf(red[tid], red[tid + o]);
        __syncthreads();
    }
    if (tid == 0) atomicMax(&g_maxb[b], __float_as_uint(red[0]));
}

// branchless sorted-5 insert
#define INS5(v) {                                   \
        float w_ = (v), t_;                         \
        t_ = fminf(b0, w_); w_ = fmaxf(b0, w_); b0 = t_; \
        t_ = fminf(b1, w_); w_ = fmaxf(b1, w_); b1 = t_; \
        t_ = fminf(b2, w_); w_ = fmaxf(b2, w_); b2 = t_; \
        t_ = fminf(b3, w_); w_ = fmaxf(b3, w_); b3 = t_; \
        b4 = fminf(b4, w_);                         \
    }

__global__ void knn_kernel() {
    int w = (blockIdx.x * blockDim.x + threadIdx.x) >> 5;
    int lane = threadIdx.x & 31;
    if (w >= B * N) return;
    const float4* row = reinterpret_cast<const float4*>(&g_d2[(size_t)w * N]);
    float b0 = 3.4e38f, b1 = 3.4e38f, b2 = 3.4e38f, b3 = 3.4e38f, b4 = 3.4e38f;
#pragma unroll 4
    for (int q = lane; q < NQ; q += 32) {
        float4 v = row[q];
        INS5(v.x); INS5(v.y); INS5(v.z); INS5(v.w);
    }
    float s = 0.f;
#pragma unroll
    for (int t = 0; t < 5; t++) {
        float m = b0;
#pragma unroll
        for (int o = 16; o > 0; o >>= 1) m = fminf(m, __shfl_xor_sync(0xffffffffu, m, o));
        unsigned bal = __ballot_sync(0xffffffffu, b0 == m);
        if (lane == (__ffs(bal) - 1)) {
            b0 = b1; b1 = b2; b2 = b3; b3 = b4; b4 = 3.4e38f;
        }
        float d = sqrtf(m) / 16.0f;
        s = s + d * d;
    }
    if (lane == 0)
        g_dens[w] = expf(-(s / 5.0f)) + jax_uniform_noise(w) * 1e-6f;
}

__global__ void parent_kernel() {
    int w = (blockIdx.x * blockDim.x + threadIdx.x) >> 5;
    int lane = threadIdx.x & 31;
    if (w >= B * N) return;
    int b = w / N;
    float di = g_dens[w];
    const float4* row = reinterpret_cast<const float4*>(&g_d2[(size_t)w * N]);
    const float4* dr  = reinterpret_cast<const float4*>(&g_dens[(size_t)b * N]);
    float mn = 3.4e38f;
#pragma unroll 4
    for (int q = lane; q < NQ; q += 32) {
        float4 v = row[q];
        float4 dd = dr[q];
        if (dd.x > di) mn = fminf(mn, v.x);
        if (dd.y > di) mn = fminf(mn, v.y);
        if (dd.z > di) mn = fminf(mn, v.z);
        if (dd.w > di) mn = fminf(mn, v.w);
    }
#pragma unroll
    for (int o = 16; o > 0; o >>= 1) mn = fminf(mn, __shfl_xor_sync(0xffffffffu, mn, o));
    if (lane == 0) {
        float dmax = sqrtf(__uint_as_float(g_maxb[b])) / 16.0f;
        float dp = fminf(dmax, sqrtf(mn) / 16.0f);
        g_score[w] = dp * di;
    }
}

// per-batch top-50 with warp-shuffle reductions (lower index wins ties)
__global__ void topk_kernel() {
    int b = blockIdx.x;
    __shared__ float s[N];
    __shared__ float wv[32];
    __shared__ int   wix[32];
    int t = threadIdx.x, lane = t & 31, w = t >> 5;
    for (int i = t; i < N; i += 1024) s[i] = g_score[b * N + i];
    __syncthreads();
    for (int m = 0; m < NC; m++) {
        float bs = -3.4e38f;
        int   bi = N;
        for (int i = t; i < N; i += 1024) {
            float v = s[i];
            if (v > bs) { bs = v; bi = i; }
        }
#pragma unroll
        for (int o = 16; o > 0; o >>= 1) {
            float ov = __shfl_xor_sync(0xffffffffu, bs, o);
            int   oi = __shfl_xor_sync(0xffffffffu, bi, o);
            if (ov > bs || (ov == bs && oi < bi)) { bs = ov; bi = oi; }
        }
        if (lane == 0) { wv[w] = bs; wix[w] = bi; }
        __syncthreads();
        if (w == 0) {
            bs = wv[lane]; bi = wix[lane];
#pragma unroll
            for (int o = 16; o > 0; o >>= 1) {
                float ov = __shfl_xor_sync(0xffffffffu, bs, o);
                int   oi = __shfl_xor_sync(0xffffffffu, bi, o);
                if (ov > bs || (ov == bs && oi < bi)) { bs = ov; bi = oi; }
            }
            if (lane == 0) { g_idx[b * NC + m] = bi; s[bi] = -3.4e38f; }
        }
        __syncthreads();
    }
}

__global__ void gather_kernel(const float* __restrict__ x, float* __restrict__ out) {
    int g = blockIdx.x * blockDim.x + threadIdx.x;
    if (g >= B * C * NC) return;
    int m = g % NC;
    int c = (g / NC) % C;
    int b = g / (NC * C);
    int idx = g_idx[b * NC + m];
    out[g] = x[(size_t)b * C * N + (size_t)c * N + idx];
}

// ---------------- launch -----------------------------------------------------
extern "C" void kernel_launch(void* const* d_in, const int* in_sizes, int n_in,
                              void* d_out, int out_size) {
    const float* x = (const float*)d_in[0];
    float* out = (float*)d_out;

    init_kernel<<<1, 32>>>();
    sq_kernel<<<(B * N + 255) / 256, 256>>>(x);
    dim3 sg(ASEGS, B);
    split_kernel<<<sg, 256>>>(x);
    dim3 gg(NPAIRS, 1, B);
    gram_kernel<<<gg, 256>>>();
    int rows = B * N;
    knn_kernel<<<(rows * 32 + 255) / 256, 256>>>();
    parent_kernel<<<(rows * 32 + 255) / 256, 256>>>();
    topk_kernel<<<B, 1024>>>();
    gather_kernel<<<(B * C * NC + 255) / 256, 256>>>(x, out);
}

// round 9
// speedup vs baseline: 1.1124x; 1.0326x over previous
#include <cuda_runtime.h>
#include <cstdint>

#define B 8
#define C 256
#define N 3136
#define NP 3200
#define NQ (N/4)
#define NC 50
#define TILE 128
#define NT 25
#define NPAIRS (NT*(NT+1)/2)
#define ASEGS 200              // NP/16
#define BSEGS 400              // NP/8
#define PC 132
#define PT 36
#define STAGE_BYTES 16384
#define NSTAGE 4
#define DSMEM_BYTES (NSTAGE*STAGE_BYTES)   // 65536

// ---------------- scratch (static device globals: allocation-guard safe) ----
__device__ float g_d2[(size_t)B * N * N];
__device__ __align__(16) float g_ah[(size_t)B * ASEGS * 32 * 128];
__device__ __align__(16) float g_al[(size_t)B * ASEGS * 32 * 128];
__device__ __align__(16) float g_bh[(size_t)B * BSEGS * 32 * 64];
__device__ __align__(16) float g_bl[(size_t)B * BSEGS * 32 * 64];
__device__ float    g_sq[B * N];
__device__ float    g_dens[B * N];
__device__ float    g_score[B * N];
__device__ unsigned g_maxb[B];
__device__ int      g_idx[B * NC];

// ---------------- threefry-2x32 (JAX-compatible) ---------------------------
__device__ __forceinline__ uint32_t rotl32(uint32_t x, int r) {
    return (x << r) | (x >> (32 - r));
}

__device__ __forceinline__ void threefry2x32_k42(uint32_t x0, uint32_t x1,
                                                 uint32_t& o0, uint32_t& o1) {
    const uint32_t ks0 = 0u;
    const uint32_t ks1 = 42u;
    const uint32_t ks2 = 0x1BD11BDAu ^ 42u;
    x0 += ks0; x1 += ks1;
#define TF_RND(r) { x0 += x1; x1 = rotl32(x1, r); x1 ^= x0; }
    TF_RND(13) TF_RND(15) TF_RND(26) TF_RND(6)
    x0 += ks1; x1 += ks2 + 1u;
    TF_RND(17) TF_RND(29) TF_RND(16) TF_RND(24)
    x0 += ks2; x1 += ks0 + 2u;
    TF_RND(13) TF_RND(15) TF_RND(26) TF_RND(6)
    x0 += ks0; x1 += ks1 + 3u;
    TF_RND(17) TF_RND(29) TF_RND(16) TF_RND(24)
    x0 += ks1; x1 += ks2 + 4u;
    TF_RND(13) TF_RND(15) TF_RND(26) TF_RND(6)
    x0 += ks2; x1 += ks0 + 5u;
#undef TF_RND
    o0 = x0; o1 = x1;
}

__device__ __forceinline__ float jax_uniform_noise(int g) {
    const int half = (B * N) / 2;  // 12544
    uint32_t lane = (g < half) ? (uint32_t)g : (uint32_t)(g - half);
    uint32_t o0, o1;
    threefry2x32_k42(lane, lane + (uint32_t)half, o0, o1);
    uint32_t bits = (g < half) ? o0 : o1;
    return __uint_as_float((bits >> 9) | 0x3F800000u) - 1.0f;
}

// ---------------- tf32 helpers ----------------------------------------------
__device__ __forceinline__ uint32_t tf32r(float x) {
    uint32_t y;
    asm("cvt.rna.tf32.f32 %0, %1;" : "=r"(y) : "f"(x));
    return y;
}

__device__ __forceinline__ void split1(float v, float& h, float& l) {
    float hf = __uint_as_float(tf32r(v));
    h = hf;
    l = __uint_as_float(tf32r(v - hf));
}

__device__ __forceinline__ void mma8(float d[4], const uint32_t a[4], const uint32_t b[2]) {
    asm volatile(
        "mma.sync.aligned.m16n8k8.row.col.f32.tf32.tf32.f32 "
        "{%0,%1,%2,%3}, {%4,%5,%6,%7}, {%8,%9}, {%0,%1,%2,%3};"
        : "+f"(d[0]), "+f"(d[1]), "+f"(d[2]), "+f"(d[3])
        : "r"(a[0]), "r"(a[1]), "r"(a[2]), "r"(a[3]), "r"(b[0]), "r"(b[1]));
}

__device__ __forceinline__ uint32_t smem_u32(const void* p) {
    uint32_t a;
    asm("{ .reg .u64 t; cvta.to.shared.u64 t, %1; cvt.u32.u64 %0, t; }"
        : "=r"(a) : "l"(p));
    return a;
}

__device__ __forceinline__ void cp16(uint32_t d, const float* s) {
    asm volatile("cp.async.cg.shared.global [%0], [%1], 16;" :: "r"(d), "l"(s));
}

// ---------------- kernels ---------------------------------------------------
__global__ void init_kernel() {
    int t = threadIdx.x;
    if (t < B) g_maxb[t] = 0u;
}

__global__ void sq_kernel(const float* __restrict__ x) {
    int g = blockIdx.x * blockDim.x + threadIdx.x;
    if (g >= B * N) return;
    int b = g / N, n = g % N;
    const float* p = x + (size_t)b * C * N + n;
    float s = 0.f;
#pragma unroll 8
    for (int c = 0; c < C; c++) {
        float v = p[(size_t)c * N];
        s = fmaf(v, v, s);
    }
    g_sq[g] = s;
}

// transpose + tf32 hi/lo split into GLOBAL FRAGMENT LAYOUTS (A-role + B-role)
__global__ void split_kernel(const float* __restrict__ x) {
    const int seg = blockIdx.x;     // 16-row segment (0..199)
    const int b = blockIdx.y;
    const int row0 = seg * 16;
    __shared__ float sv[16][260];
    const int t = threadIdx.x;
#pragma unroll
    for (int i = 0; i < 16; i++) {
        int r = t & 15;
        int k = (t >> 4) + i * 16;
        int row = row0 + r;
        float v = (row < N) ? x[((size_t)b * C + k) * N + row] : 0.f;
        sv[r][k] = v;
    }
    __syncthreads();
    // A-role: [seg][k8][lane][reg0..3]
#pragma unroll
    for (int j = 0; j < 4; j++) {
        int u = t + j * 256;
        int k8 = u >> 5, lane = u & 31;
        int rl = lane >> 2, tg = lane & 3;
        int k = k8 * 8 + tg;
        float4 hv, lv;
        split1(sv[rl][k],         hv.x, lv.x);
        split1(sv[rl + 8][k],     hv.y, lv.y);
        split1(sv[rl][k + 4],     hv.z, lv.z);
        split1(sv[rl + 8][k + 4], hv.w, lv.w);
        size_t base = (((size_t)b * ASEGS + seg) * 32 + k8) * 128 + lane * 4;
        *reinterpret_cast<float4*>(&g_ah[base]) = hv;
        *reinterpret_cast<float4*>(&g_al[base]) = lv;
    }
    // B-role: [colseg][k8][lane][reg0..1]
#pragma unroll
    for (int j = 0; j < 8; j++) {
        int u = t + j * 256;
        int cs = u >> 10, rem = u & 1023;
        int k8 = rem >> 5, lane = rem & 31;
        int col = cs * 8 + (lane >> 2), tg = lane & 3;
        int k = k8 * 8 + tg;
        float2 hv, lv;
        split1(sv[col][k],     hv.x, lv.x);
        split1(sv[col][k + 4], hv.y, lv.y);
        size_t base = (((size_t)b * BSEGS + seg * 2 + cs) * 32 + k8) * 64 + lane * 2;
        *reinterpret_cast<float2*>(&g_bh[base]) = hv;
        *reinterpret_cast<float2*>(&g_bl[base]) = lv;
    }
}

// Symmetric Gram via tf32x3 mma.sync.
// 128x128 CTA tile, 4 warps of 64x64 (2x2 warp grid), 4-stage cp.async pipeline.
__global__ __launch_bounds__(128, 2) void gram_kernel() {
    extern __shared__ char dyn[];
    __shared__ float red[128];

    const int b = blockIdx.z;
    int rem = blockIdx.x;
    int ti = 0;
    while (rem >= NT - ti) { rem -= NT - ti; ti++; }
    const int tj = ti + rem;
    const int i0 = ti * TILE, j0 = tj * TILE;

    const int tid = threadIdx.x, lane = tid & 31, wid = tid >> 5;
    const int wr = wid >> 1, wc = wid & 1;          // 2x2 warp grid
    const int kq = lane & 3, rr = lane >> 2;
    const uint32_t smb = smem_u32(dyn);

    // gmem fragment bases (floats)
    const float* Ah = g_ah + ((size_t)b * ASEGS + ti * 8) * 4096;
    const float* Al = g_al + ((size_t)b * ASEGS + ti * 8) * 4096;
    const float* Bh = g_bh + ((size_t)b * BSEGS + tj * 16) * 2048;
    const float* Bl = g_bl + ((size_t)b * BSEGS + tj * 16) * 2048;

    // per-thread cp.async chunk offsets (j = 0..7, u = tid + j*128)
    const int wA0 = tid, wA1 = tid + 128;            // A-region chunk ids (0..255)
    const int aof0 = (wA0 >> 5) * 4096 + (wA0 & 31) * 4;
    const int aof1 = (wA1 >> 5) * 4096 + (wA1 & 31) * 4;
    const int bof0 = (wA0 >> 4) * 2048 + (wA0 & 15) * 4;
    const int bof1 = (wA1 >> 4) * 2048 + (wA1 & 15) * 4;

#define ISSUE(s) {                                                    \
        uint32_t sb = smb + ((s) & 3) * STAGE_BYTES;                  \
        int ka = (s) * 128, kb = (s) * 64;                            \
        cp16(sb + wA0 * 16,                 Ah + aof0 + ka);          \
        cp16(sb + wA1 * 16,                 Ah + aof1 + ka);          \
        cp16(sb + 4096 + wA0 * 16,          Al + aof0 + ka);          \
        cp16(sb + 4096 + wA1 * 16,          Al + aof1 + ka);          \
        cp16(sb + 8192 + wA0 * 16,          Bh + bof0 + kb);          \
        cp16(sb + 8192 + wA1 * 16,          Bh + bof1 + kb);          \
        cp16(sb + 12288 + wA0 * 16,         Bl + bof0 + kb);          \
        cp16(sb + 12288 + wA1 * 16,         Bl + bof1 + kb);          \
        asm volatile("cp.async.commit_group;");                       \
    }

    float D[4][8][4];
#pragma unroll
    for (int mf = 0; mf < 4; mf++)
#pragma unroll
        for (int nf = 0; nf < 8; nf++)
#pragma unroll
            for (int e = 0; e < 4; e++) D[mf][nf][e] = 0.f;

    ISSUE(0); ISSUE(1); ISSUE(2);

#pragma unroll 1
    for (int kc = 0; kc < 32; kc++) {
        asm volatile("cp.async.wait_group 2;");
        __syncthreads();
        if (kc + 3 < 32) ISSUE(kc + 3);

        const char* sb = dyn + (kc & 3) * STAGE_BYTES;
        // B frags for this warp (8 nf, hi+lo)
        uint2 BHf[8], BLf[8];
#pragma unroll
        for (int nf = 0; nf < 8; nf++) {
            int off = 8192 + (wc * 8 + nf) * 256 + lane * 8;
            BHf[nf] = *reinterpret_cast<const uint2*>(sb + off);
            BLf[nf] = *reinterpret_cast<const uint2*>(sb + off + 4096);
        }
#pragma unroll
        for (int mf = 0; mf < 4; mf++) {
            int aoff = (wr * 4 + mf) * 512 + lane * 16;
            uint4 AHf = *reinterpret_cast<const uint4*>(sb + aoff);
            uint4 ALf = *reinterpret_cast<const uint4*>(sb + aoff + 4096);
            uint32_t ah[4] = {AHf.x, AHf.y, AHf.z, AHf.w};
            uint32_t al[4] = {ALf.x, ALf.y, ALf.z, ALf.w};
#pragma unroll
            for (int nf = 0; nf < 8; nf++) {
                uint32_t bh[2] = {BHf[nf].x, BHf[nf].y};
                uint32_t bl[2] = {BLf[nf].x, BLf[nf].y};
                mma8(D[mf][nf], ah, bl);
                mma8(D[mf][nf], al, bh);
                mma8(D[mf][nf], ah, bh);
            }
        }
    }
#undef ISSUE

    // ---------------- epilogue: 4 chunks of 32 i-rows, staged via smem -------
    float* Cs = reinterpret_cast<float*>(dyn);            // 32 x PC
    float* Cst = reinterpret_cast<float*>(dyn) + 32 * PC; // 128 x PT
    const float* SQ = &g_sq[b * N];
    const size_t bN = (size_t)b * N;
    float tmax = 0.f;

    for (int g5 = 0; g5 < 4; g5++) {
        __syncthreads();
        if (wr == (g5 >> 1)) {
            int mbase = (g5 & 1) * 2;
#pragma unroll
            for (int mm = 0; mm < 2; mm++) {
                int mf = mbase + mm;
                int lr = mm * 16 + rr;
#pragma unroll
                for (int nf = 0; nf < 8; nf++) {
                    int cb = wc * 64 + nf * 8 + 2 * kq;
                    float e0 = D[mf][nf][0], e1 = D[mf][nf][1];
                    float e2 = D[mf][nf][2], e3 = D[mf][nf][3];
                    Cs[lr * PC + cb] = e0;          Cs[lr * PC + cb + 1] = e1;
                    Cs[(lr + 8) * PC + cb] = e2;    Cs[(lr + 8) * PC + cb + 1] = e3;
                    Cst[cb * PT + lr] = e0;         Cst[(cb + 1) * PT + lr] = e1;
                    Cst[cb * PT + lr + 8] = e2;     Cst[(cb + 1) * PT + lr + 8] = e3;
                }
            }
        }
        __syncthreads();

#pragma unroll
        for (int w2 = 0; w2 < 8; w2++) {
            int slot = tid + 128 * w2;        // 1024 slots = 32 rows x 32 float4
            int jr = slot >> 5, q4 = slot & 31;
            int gi = i0 + g5 * 32 + jr, gj = j0 + q4 * 4;
            if (gi < N && gj < N) {
                float sqi = SQ[gi];
                float4 v = *reinterpret_cast<float4*>(&Cs[jr * PC + q4 * 4]);
                float4 o;
                o.x = fmaxf(sqi + SQ[gj + 0] - 2.f * v.x, 0.f);
                o.y = fmaxf(sqi + SQ[gj + 1] - 2.f * v.y, 0.f);
                o.z = fmaxf(sqi + SQ[gj + 2] - 2.f * v.z, 0.f);
                o.w = fmaxf(sqi + SQ[gj + 3] - 2.f * v.w, 0.f);
                tmax = fmaxf(tmax, fmaxf(fmaxf(o.x, o.y), fmaxf(o.z, o.w)));
                *reinterpret_cast<float4*>(&g_d2[(bN + gi) * N + gj]) = o;
            }
        }
        if (ti != tj) {
#pragma unroll
            for (int w2 = 0; w2 < 8; w2++) {
                int slot = tid + 128 * w2;    // 1024 slots = 128 rows x 8 float4
                int jr2 = slot >> 3, q42 = slot & 7;
                int gj = j0 + jr2, gi = i0 + g5 * 32 + q42 * 4;
                if (gj < N && gi < N) {
                    float sqj = SQ[gj];
                    float4 v = *reinterpret_cast<float4*>(&Cst[jr2 * PT + q42 * 4]);
                    float4 o;
                    o.x = fmaxf(SQ[gi + 0] + sqj - 2.f * v.x, 0.f);
                    o.y = fmaxf(SQ[gi + 1] + sqj - 2.f * v.y, 0.f);
                    o.z = fmaxf(SQ[gi + 2] + sqj - 2.f * v.z, 0.f);
                    o.w = fmaxf(SQ[gi + 3] + sqj - 2.f * v.w, 0.f);
                    *reinterpret_cast<float4*>(&g_d2[(bN + gj) * N + gi]) = o;
                }
            }
        }
    }

    red[tid] = tmax;
    __syncthreads();
    for (int o = 64; o > 0; o >>= 1) {
        if (tid < o) red[tid] = fmaxf(red[tid], red[tid + o]);
        __syncthreads();
    }
    if (tid == 0) atomicMax(&g_maxb[b], __float_as_uint(red[0]));
}

// branchless sorted-5 insert
#define INS5(v) {                                   \
        float w_ = (v), t_;                         \
        t_ = fminf(b0, w_); w_ = fmaxf(b0, w_); b0 = t_; \
        t_ = fminf(b1, w_); w_ = fmaxf(b1, w_); b1 = t_; \
        t_ = fminf(b2, w_); w_ = fmaxf(b2, w_); b2 = t_; \
        t_ = fminf(b3, w_); w_ = fmaxf(b3, w_); b3 = t_; \
        b4 = fminf(b4, w_);                         \
    }

__global__ void knn_kernel() {
    int w = (blockIdx.x * blockDim.x + threadIdx.x) >> 5;
    int lane = threadIdx.x & 31;
    if (w >= B * N) return;
    const float4* row = reinterpret_cast<const float4*>(&g_d2[(size_t)w * N]);
    float b0 = 3.4e38f, b1 = 3.4e38f, b2 = 3.4e38f, b3 = 3.4e38f, b4 = 3.4e38f;
#pragma unroll 4
    for (int q = lane; q < NQ; q += 32) {
        float4 v = row[q];
        INS5(v.x); INS5(v.y); INS5(v.z); INS5(v.w);
    }
    float s = 0.f;
#pragma unroll
    for (int t = 0; t < 5; t++) {
        float m = b0;
#pragma unroll
        for (int o = 16; o > 0; o >>= 1) m = fminf(m, __shfl_xor_sync(0xffffffffu, m, o));
        unsigned bal = __ballot_sync(0xffffffffu, b0 == m);
        if (lane == (__ffs(bal) - 1)) {
            b0 = b1; b1 = b2; b2 = b3; b3 = b4; b4 = 3.4e38f;
        }
        float d = sqrtf(m) / 16.0f;
        s = s + d * d;
    }
    if (lane == 0)
        g_dens[w] = expf(-(s / 5.0f)) + jax_uniform_noise(w) * 1e-6f;
}

__global__ void parent_kernel() {
    int w = (blockIdx.x * blockDim.x + threadIdx.x) >> 5;
    int lane = threadIdx.x & 31;
    if (w >= B * N) return;
    int b = w / N;
    float di = g_dens[w];
    const float4* row = reinterpret_cast<const float4*>(&g_d2[(size_t)w * N]);
    const float4* dr  = reinterpret_cast<const float4*>(&g_dens[(size_t)b * N]);
    float mn = 3.4e38f;
#pragma unroll 4
    for (int q = lane; q < NQ; q += 32) {
        float4 v = row[q];
        float4 dd = dr[q];
        if (dd.x > di) mn = fminf(mn, v.x);
        if (dd.y > di) mn = fminf(mn, v.y);
        if (dd.z > di) mn = fminf(mn, v.z);
        if (dd.w > di) mn = fminf(mn, v.w);
    }
#pragma unroll
    for (int o = 16; o > 0; o >>= 1) mn = fminf(mn, __shfl_xor_sync(0xffffffffu, mn, o));
    if (lane == 0) {
        float dmax = sqrtf(__uint_as_float(g_maxb[b])) / 16.0f;
        float dp = fminf(dmax, sqrtf(mn) / 16.0f);
        g_score[w] = dp * di;
    }
}

// per-batch top-50 with warp-shuffle reductions (lower index wins ties)
__global__ void topk_kernel() {
    int b = blockIdx.x;
    __shared__ float s[N];
    __shared__ float wv[32];
    __shared__ int   wix[32];
    int t = threadIdx.x, lane = t & 31, w = t >> 5;
    for (int i = t; i < N; i += 1024) s[i] = g_score[b * N + i];
    __syncthreads();
    for (int m = 0; m < NC; m++) {
        float bs = -3.4e38f;
        int   bi = N;
        for (int i = t; i < N; i += 1024) {
            float v = s[i];
            if (v > bs) { bs = v; bi = i; }
        }
#pragma unroll
        for (int o = 16; o > 0; o >>= 1) {
            float ov = __shfl_xor_sync(0xffffffffu, bs, o);
            int   oi = __shfl_xor_sync(0xffffffffu, bi, o);
            if (ov > bs || (ov == bs && oi < bi)) { bs = ov; bi = oi; }
        }
        if (lane == 0) { wv[w] = bs; wix[w] = bi; }
        __syncthreads();
        if (w == 0) {
            bs = wv[lane]; bi = wix[lane];
#pragma unroll
            for (int o = 16; o > 0; o >>= 1) {
                float ov = __shfl_xor_sync(0xffffffffu, bs, o);
                int   oi = __shfl_xor_sync(0xffffffffu, bi, o);
                if (ov > bs || (ov == bs && oi < bi)) { bs = ov; bi = oi; }
            }
            if (lane == 0) { g_idx[b * NC + m] = bi; s[bi] = -3.4e38f; }
        }
        __syncthreads();
    }
}

__global__ void gather_kernel(const float* __restrict__ x, float* __restrict__ out) {
    int g = blockIdx.x * blockDim.x + threadIdx.x;
    if (g >= B * C * NC) return;
    int m = g % NC;
    int c = (g / NC) % C;
    int b = g / (NC * C);
    int idx = g_idx[b * NC + m];
    out[g] = x[(size_t)b * C * N + (size_t)c * N + idx];
}

// ---------------- launch -----------------------------------------------------
extern "C" void kernel_launch(void* const* d_in, const int* in_sizes, int n_in,
                              void* d_out, int out_size) {
    const float* x = (const float*)d_in[0];
    float* out = (float*)d_out;

    cudaFuncSetAttribute(gram_kernel,
                         cudaFuncAttributeMaxDynamicSharedMemorySize, DSMEM_BYTES);

    init_kernel<<<1, 32>>>();
    sq_kernel<<<(B * N + 255) / 256, 256>>>(x);
    dim3 sg(ASEGS, B);
    split_kernel<<<sg, 256>>>(x);
    dim3 gg(NPAIRS, 1, B);
    gram_kernel<<<gg, 128, DSMEM_BYTES>>>();
    int rows = B * N;
    knn_kernel<<<(rows * 32 + 255) / 256, 256>>>();
    parent_kernel<<<(rows * 32 + 255) / 256, 256>>>();
    topk_kernel<<<B, 1024>>>();
    gather_kernel<<<(B * C * NC + 255) / 256, 256>>>(x, out);
}

// round 10
// speedup vs baseline: 1.3102x; 1.1778x over previous
#include <cuda_runtime.h>
#include <cstdint>

#define B 8
#define C 256
#define N 3136
#define NP 3200
#define NQ (N/4)
#define NC 50
#define TILE 128
#define KT 16
#define NT 25
#define NPAIRS (NT*(NT+1)/2)
#define ASEGS 200              // NP/16
#define BSEGS 400              // NP/8
#define PC 132
#define PT 36
#define DSMEM_BYTES 41984      // max(fp32: 4096+4096+2064 floats = 41024, tensor: 35328)

// ---------------- scratch (static device globals: allocation-guard safe) ----
__device__ float g_d2[(size_t)B * N * N];
__device__ __align__(16) float g_ah[(size_t)B * ASEGS * 32 * 128];
__device__ __align__(16) float g_al[(size_t)B * ASEGS * 32 * 128];
__device__ __align__(16) float g_bh[(size_t)B * BSEGS * 32 * 64];
__device__ __align__(16) float g_bl[(size_t)B * BSEGS * 32 * 64];
__device__ float    g_sq[B * N];
__device__ float    g_dens[B * N];
__device__ float    g_score[B * N];
__device__ unsigned g_maxb[B];
__device__ int      g_idx[B * NC];

// ---------------- threefry-2x32 (JAX-compatible) ---------------------------
__device__ __forceinline__ uint32_t rotl32(uint32_t x, int r) {
    return (x << r) | (x >> (32 - r));
}

__device__ __forceinline__ void threefry2x32_k42(uint32_t x0, uint32_t x1,
                                                 uint32_t& o0, uint32_t& o1) {
    const uint32_t ks0 = 0u;
    const uint32_t ks1 = 42u;
    const uint32_t ks2 = 0x1BD11BDAu ^ 42u;
    x0 += ks0; x1 += ks1;
#define TF_RND(r) { x0 += x1; x1 = rotl32(x1, r); x1 ^= x0; }
    TF_RND(13) TF_RND(15) TF_RND(26) TF_RND(6)
    x0 += ks1; x1 += ks2 + 1u;
    TF_RND(17) TF_RND(29) TF_RND(16) TF_RND(24)
    x0 += ks2; x1 += ks0 + 2u;
    TF_RND(13) TF_RND(15) TF_RND(26) TF_RND(6)
    x0 += ks0; x1 += ks1 + 3u;
    TF_RND(17) TF_RND(29) TF_RND(16) TF_RND(24)
    x0 += ks1; x1 += ks2 + 4u;
    TF_RND(13) TF_RND(15) TF_RND(26) TF_RND(6)
    x0 += ks2; x1 += ks0 + 5u;
#undef TF_RND
    o0 = x0; o1 = x1;
}

__device__ __forceinline__ float jax_uniform_noise(int g) {
    const int half = (B * N) / 2;  // 12544
    uint32_t lane = (g < half) ? (uint32_t)g : (uint32_t)(g - half);
    uint32_t o0, o1;
    threefry2x32_k42(lane, lane + (uint32_t)half, o0, o1);
    uint32_t bits = (g < half) ? o0 : o1;
    return __uint_as_float((bits >> 9) | 0x3F800000u) - 1.0f;
}

// ---------------- tf32 + f32x2 helpers ---------------------------------------
__device__ __forceinline__ uint32_t tf32r(float x) {
    uint32_t y;
    asm("cvt.rna.tf32.f32 %0, %1;" : "=r"(y) : "f"(x));
    return y;
}

__device__ __forceinline__ void split1(float v, float& h, float& l) {
    float hf = __uint_as_float(tf32r(v));
    h = hf;
    l = __uint_as_float(tf32r(v - hf));
}

__device__ __forceinline__ void mma8(float d[4], const uint32_t a[4], const uint32_t b[2]) {
    asm volatile(
        "mma.sync.aligned.m16n8k8.row.col.f32.tf32.tf32.f32 "
        "{%0,%1,%2,%3}, {%4,%5,%6,%7}, {%8,%9}, {%0,%1,%2,%3};"
        : "+f"(d[0]), "+f"(d[1]), "+f"(d[2]), "+f"(d[3])
        : "r"(a[0]), "r"(a[1]), "r"(a[2]), "r"(a[3]), "r"(b[0]), "r"(b[1]));
}

__device__ __forceinline__ unsigned long long ffma2(unsigned long long a,
                                                    unsigned long long b,
                                                    unsigned long long c) {
    unsigned long long d;
    asm("fma.rn.f32x2 %0, %1, %2, %3;" : "=l"(d) : "l"(a), "l"(b), "l"(c));
    return d;
}

__device__ __forceinline__ unsigned long long dup2(float a) {
    unsigned long long d;
    asm("mov.b64 %0, {%1, %1};" : "=l"(d) : "f"(a));
    return d;
}

// ---------------- kernels ---------------------------------------------------
__global__ void init_kernel() {
    int t = threadIdx.x;
    if (t < B) g_maxb[t] = 0u;
}

__global__ void sq_kernel(const float* __restrict__ x) {
    int g = blockIdx.x * blockDim.x + threadIdx.x;
    if (g >= B * N) return;
    int b = g / N, n = g % N;
    const float* p = x + (size_t)b * C * N + n;
    float s = 0.f;
#pragma unroll 8
    for (int c = 0; c < C; c++) {
        float v = p[(size_t)c * N];
        s = fmaf(v, v, s);
    }
    g_sq[g] = s;
}

// transpose + tf32 hi/lo split into global fragment layouts (tensor-path operands)
__global__ void split_kernel(const float* __restrict__ x) {
    const int seg = blockIdx.x;
    const int b = blockIdx.y;
    const int row0 = seg * 16;
    __shared__ float sv[16][260];
    const int t = threadIdx.x;
#pragma unroll
    for (int i = 0; i < 16; i++) {
        int r = t & 15;
        int k = (t >> 4) + i * 16;
        int row = row0 + r;
        float v = (row < N) ? x[((size_t)b * C + k) * N + row] : 0.f;
        sv[r][k] = v;
    }
    __syncthreads();
#pragma unroll
    for (int j = 0; j < 4; j++) {
        int u = t + j * 256;
        int k8 = u >> 5, lane = u & 31;
        int rl = lane >> 2, tg = lane & 3;
        int k = k8 * 8 + tg;
        float4 hv, lv;
        split1(sv[rl][k],         hv.x, lv.x);
        split1(sv[rl + 8][k],     hv.y, lv.y);
        split1(sv[rl][k + 4],     hv.z, lv.z);
        split1(sv[rl + 8][k + 4], hv.w, lv.w);
        size_t base = (((size_t)b * ASEGS + seg) * 32 + k8) * 128 + lane * 4;
        *reinterpret_cast<float4*>(&g_ah[base]) = hv;
        *reinterpret_cast<float4*>(&g_al[base]) = lv;
    }
#pragma unroll
    for (int j = 0; j < 8; j++) {
        int u = t + j * 256;
        int cs = u >> 10, rem = u & 1023;
        int k8 = rem >> 5, lane = rem & 31;
        int col = cs * 8 + (lane >> 2), tg = lane & 3;
        int k = k8 * 8 + tg;
        float2 hv, lv;
        split1(sv[col][k],     hv.x, lv.x);
        split1(sv[col][k + 4], hv.y, lv.y);
        size_t base = (((size_t)b * BSEGS + seg * 2 + cs) * 32 + k8) * 64 + lane * 2;
        *reinterpret_cast<float2*>(&g_bh[base]) = hv;
        *reinterpret_cast<float2*>(&g_bl[base]) = lv;
    }
}

// HYBRID Gram: CTA-level branch — 3/8 of tile-pairs use tf32x3 mma.sync (tensor
// pipe), 5/8 use fp32 f32x2 FFMA (fma pipe). Both paths previously verified.
__global__ __launch_bounds__(256, 2) void gram_kernel(const float* __restrict__ x) {
    extern __shared__ float dynf[];
    __shared__ float red[256];

    const int b = blockIdx.z;
    int rem = blockIdx.x;
    int ti = 0;
    while (rem >= NT - ti) { rem -= NT - ti; ti++; }
    const int tj = ti + rem;
    const int i0 = ti * TILE, j0 = tj * TILE;

    const int tid = threadIdx.x, lane = tid & 31, wid = tid >> 5;
    const float* SQ = &g_sq[b * N];
    const size_t bN = (size_t)b * N;
    float tmax = 0.f;

    if ((blockIdx.x & 7) < 3) {
        // ===================== TENSOR PATH (R8, verified) =====================
        float* Cs = dynf;                 // 32 x PC
        float* Cst = dynf + 32 * PC;      // 128 x PT
        const int wr = wid >> 2, wc = wid & 3;
        const int kq = lane & 3, rr = lane >> 2;

        const uint4* pah = reinterpret_cast<const uint4*>(
            g_ah + ((size_t)b * ASEGS + ti * 8 + wr * 4) * 4096) + lane;
        const uint4* pal = reinterpret_cast<const uint4*>(
            g_al + ((size_t)b * ASEGS + ti * 8 + wr * 4) * 4096) + lane;
        const uint2* pbh = reinterpret_cast<const uint2*>(
            g_bh + ((size_t)b * BSEGS + tj * 16 + wc * 4) * 2048) + lane;
        const uint2* pbl = reinterpret_cast<const uint2*>(
            g_bl + ((size_t)b * BSEGS + tj * 16 + wc * 4) * 2048) + lane;

        float D[4][4][4];
#pragma unroll
        for (int mf = 0; mf < 4; mf++)
#pragma unroll
            for (int nf = 0; nf < 4; nf++)
#pragma unroll
                for (int e = 0; e < 4; e++) D[mf][nf][e] = 0.f;

#pragma unroll 2
        for (int k8 = 0; k8 < 32; k8++) {
            uint4 AH[4], AL[4];
            uint2 BH[4], BL[4];
#pragma unroll
            for (int mf = 0; mf < 4; mf++) {
                AH[mf] = pah[mf * 1024];
                AL[mf] = pal[mf * 1024];
            }
#pragma unroll
            for (int nf = 0; nf < 4; nf++) {
                BH[nf] = pbh[nf * 1024];
                BL[nf] = pbl[nf * 1024];
            }
            pah += 32; pal += 32; pbh += 32; pbl += 32;
#pragma unroll
            for (int mf = 0; mf < 4; mf++) {
                uint32_t ah[4] = {AH[mf].x, AH[mf].y, AH[mf].z, AH[mf].w};
                uint32_t al[4] = {AL[mf].x, AL[mf].y, AL[mf].z, AL[mf].w};
#pragma unroll
                for (int nf = 0; nf < 4; nf++) {
                    uint32_t bh[2] = {BH[nf].x, BH[nf].y};
                    uint32_t bl[2] = {BL[nf].x, BL[nf].y};
                    mma8(D[mf][nf], ah, bl);
                    mma8(D[mf][nf], al, bh);
                    mma8(D[mf][nf], ah, bh);
                }
            }
        }

        for (int g5 = 0; g5 < 4; g5++) {
            __syncthreads();
            if (wr == (g5 >> 1)) {
                int mbase = (g5 & 1) * 2;
#pragma unroll
                for (int mm = 0; mm < 2; mm++) {
                    int mf = mbase + mm;
                    int lr = mm * 16 + rr;
#pragma unroll
                    for (int nf = 0; nf < 4; nf++) {
                        int cb = wc * 32 + nf * 8 + 2 * kq;
                        float e0 = D[mf][nf][0], e1 = D[mf][nf][1];
                        float e2 = D[mf][nf][2], e3 = D[mf][nf][3];
                        Cs[lr * PC + cb] = e0;          Cs[lr * PC + cb + 1] = e1;
                        Cs[(lr + 8) * PC + cb] = e2;    Cs[(lr + 8) * PC + cb + 1] = e3;
                        Cst[cb * PT + lr] = e0;         Cst[(cb + 1) * PT + lr] = e1;
                        Cst[cb * PT + lr + 8] = e2;     Cst[(cb + 1) * PT + lr + 8] = e3;
                    }
                }
            }
            __syncthreads();

#pragma unroll
            for (int w2 = 0; w2 < 4; w2++) {
                int slot = tid + 256 * w2;
                int jr = slot >> 5, q4 = slot & 31;
                int gi = i0 + g5 * 32 + jr, gj = j0 + q4 * 4;
                if (gi < N && gj < N) {
                    float sqi = SQ[gi];
                    float4 v = *reinterpret_cast<float4*>(&Cs[jr * PC + q4 * 4]);
                    float4 o;
                    o.x = fmaxf(sqi + SQ[gj + 0] - 2.f * v.x, 0.f);
                    o.y = fmaxf(sqi + SQ[gj + 1] - 2.f * v.y, 0.f);
                    o.z = fmaxf(sqi + SQ[gj + 2] - 2.f * v.z, 0.f);
                    o.w = fmaxf(sqi + SQ[gj + 3] - 2.f * v.w, 0.f);
                    tmax = fmaxf(tmax, fmaxf(fmaxf(o.x, o.y), fmaxf(o.z, o.w)));
                    *reinterpret_cast<float4*>(&g_d2[(bN + gi) * N + gj]) = o;
                }
            }
            if (ti != tj) {
#pragma unroll
                for (int w2 = 0; w2 < 4; w2++) {
                    int slot = tid + 256 * w2;
                    int jr2 = slot >> 3, q42 = slot & 7;
                    int gj = j0 + jr2, gi = i0 + g5 * 32 + q42 * 4;
                    if (gj < N && gi < N) {
                        float sqj = SQ[gj];
                        float4 v = *reinterpret_cast<float4*>(&Cst[jr2 * PT + q42 * 4]);
                        float4 o;
                        o.x = fmaxf(SQ[gi + 0] + sqj - 2.f * v.x, 0.f);
                        o.y = fmaxf(SQ[gi + 1] + sqj - 2.f * v.y, 0.f);
                        o.z = fmaxf(SQ[gi + 2] + sqj - 2.f * v.z, 0.f);
                        o.w = fmaxf(SQ[gi + 3] + sqj - 2.f * v.w, 0.f);
                        *reinterpret_cast<float4*>(&g_d2[(bN + gj) * N + gi]) = o;
                    }
                }
            }
        }
    } else {
        // ===================== FP32 PATH (R4, verified) =======================
        // dyn layout: As = [0,4096) floats (2 bufs x 16 x 128), Bs = [4096,8192),
        //             Ts = [8192, 8192+2064)
        float* Asb = dynf;
        float* Bsb = dynf + 4096;
        float* Ts  = dynf + 8192;       // 16 x 129
        const float* X = x + (size_t)b * C * N;

        const int tx = tid & 15;
        const int ty = tid >> 4;
        const int kk0 = tid >> 5;
        const int kk1 = (tid + 256) >> 5;
        const int f4  = tid & 31;
        const int icol = i0 + f4 * 4;
        const int jcol = j0 + f4 * 4;
        const bool iok = (icol < N);
        const bool jok2 = (jcol < N);

        float4 pa0, pa1, pb0, pb1;
#define LOADK(k0) {                                                          \
            pa0 = pa1 = pb0 = pb1 = make_float4(0.f, 0.f, 0.f, 0.f);         \
            if (iok) {                                                       \
                pa0 = *reinterpret_cast<const float4*>(&X[(size_t)((k0) + kk0) * N + icol]); \
                pa1 = *reinterpret_cast<const float4*>(&X[(size_t)((k0) + kk1) * N + icol]); \
            }                                                                \
            if (jok2) {                                                      \
                pb0 = *reinterpret_cast<const float4*>(&X[(size_t)((k0) + kk0) * N + jcol]); \
                pb1 = *reinterpret_cast<const float4*>(&X[(size_t)((k0) + kk1) * N + jcol]); \
            }                                                                \
        }

        unsigned long long acc2[8][4];
#pragma unroll
        for (int r = 0; r < 8; r++)
#pragma unroll
            for (int c = 0; c < 4; c++) acc2[r][c] = 0ull;

        LOADK(0);
#pragma unroll 2
        for (int kt = 0; kt < C / KT; kt++) {
            const int bo = (kt & 1) * 2048;
            *reinterpret_cast<float4*>(&Asb[bo + kk0 * 128 + f4 * 4]) = pa0;
            *reinterpret_cast<float4*>(&Asb[bo + kk1 * 128 + f4 * 4]) = pa1;
            *reinterpret_cast<float4*>(&Bsb[bo + kk0 * 128 + f4 * 4]) = pb0;
            *reinterpret_cast<float4*>(&Bsb[bo + kk1 * 128 + f4 * 4]) = pb1;
            __syncthreads();
            if (kt + 1 < C / KT) LOADK((kt + 1) * KT);
#pragma unroll
            for (int kk = 0; kk < KT; kk++) {
                float a[8];
                *reinterpret_cast<float4*>(&a[0]) =
                    *reinterpret_cast<float4*>(&Asb[bo + kk * 128 + ty * 8]);
                *reinterpret_cast<float4*>(&a[4]) =
                    *reinterpret_cast<float4*>(&Asb[bo + kk * 128 + ty * 8 + 4]);
                ulonglong2 bp0 = *reinterpret_cast<ulonglong2*>(&Bsb[bo + kk * 128 + tx * 8]);
                ulonglong2 bp1 = *reinterpret_cast<ulonglong2*>(&Bsb[bo + kk * 128 + tx * 8 + 4]);
#pragma unroll
                for (int r = 0; r < 8; r++) {
                    unsigned long long ad = dup2(a[r]);
                    acc2[r][0] = ffma2(ad, bp0.x, acc2[r][0]);
                    acc2[r][1] = ffma2(ad, bp0.y, acc2[r][1]);
                    acc2[r][2] = ffma2(ad, bp1.x, acc2[r][2]);
                    acc2[r][3] = ffma2(ad, bp1.y, acc2[r][3]);
                }
            }
            __syncthreads();
        }
#undef LOADK

        float acc[8][8];
#pragma unroll
        for (int r = 0; r < 8; r++)
#pragma unroll
            for (int c = 0; c < 4; c++) {
                unsigned long long v = acc2[r][c];
                acc[r][2 * c]     = __uint_as_float((uint32_t)(v & 0xffffffffu));
                acc[r][2 * c + 1] = __uint_as_float((uint32_t)(v >> 32));
            }

        float sqi[8], sqj[8];
        const int jb = j0 + tx * 8;
        const bool jwr = (jb < N);
#pragma unroll
        for (int r = 0; r < 8; r++) {
            int gi = i0 + ty * 8 + r;
            sqi[r] = (gi < N) ? SQ[gi] : 0.f;
        }
#pragma unroll
        for (int c = 0; c < 8; c++) {
            int gj = jb + c;
            sqj[c] = (gj < N) ? SQ[gj] : 0.f;
        }
#pragma unroll
        for (int r = 0; r < 8; r++) {
#pragma unroll
            for (int c = 0; c < 8; c++)
                acc[r][c] = fmaxf(sqi[r] + sqj[c] - 2.f * acc[r][c], 0.f);
            int gi = i0 + ty * 8 + r;
            if (gi < N && jwr) {
#pragma unroll
                for (int c = 0; c < 8; c++) tmax = fmaxf(tmax, acc[r][c]);
                float* dst = &g_d2[(bN + gi) * N + jb];
                *reinterpret_cast<float4*>(dst)     = *reinterpret_cast<float4*>(&acc[r][0]);
                *reinterpret_cast<float4*>(dst + 4) = *reinterpret_cast<float4*>(&acc[r][4]);
            }
        }

        if (ti != tj) {
            for (int s = 0; s < 8; s++) {
                __syncthreads();
                if ((tx >> 1) == s) {
#pragma unroll
                    for (int c = 0; c < 8; c++)
#pragma unroll
                        for (int r = 0; r < 8; r++)
                            Ts[((tx & 1) * 8 + c) * 129 + ty * 8 + r] = acc[r][c];
                }
                __syncthreads();
#pragma unroll
                for (int w2 = 0; w2 < 2; w2++) {
                    int slot = tid + 256 * w2;
                    int jr = slot >> 5;
                    int q4 = slot & 31;
                    int gj = j0 + s * 16 + jr;
                    int gi = i0 + q4 * 4;
                    if (gj < N && gi < N) {
                        float4 v = make_float4(Ts[jr * 129 + q4 * 4],
                                               Ts[jr * 129 + q4 * 4 + 1],
                                               Ts[jr * 129 + q4 * 4 + 2],
                                               Ts[jr * 129 + q4 * 4 + 3]);
                        *reinterpret_cast<float4*>(&g_d2[(bN + gj) * N + gi]) = v;
                    }
                }
            }
        }
    }

    // block max -> one atomic per block (both paths)
    red[tid] = tmax;
    __syncthreads();
    for (int o = 128; o > 0; o >>= 1) {
        if (tid < o) red[tid] = fmaxf(red[tid], red[tid + o]);
        __syncthreads();
    }
    if (tid == 0) atomicMax(&g_maxb[b], __float_as_uint(red[0]));
}

// branchless sorted-5 insert
#define INS5(v) {                                   \
        float w_ = (v), t_;                         \
        t_ = fminf(b0, w_); w_ = fmaxf(b0, w_); b0 = t_; \
        t_ = fminf(b1, w_); w_ = fmaxf(b1, w_); b1 = t_; \
        t_ = fminf(b2, w_); w_ = fmaxf(b2, w_); b2 = t_; \
        t_ = fminf(b3, w_); w_ = fmaxf(b3, w_); b3 = t_; \
        b4 = fminf(b4, w_);                         \
    }

__global__ void knn_kernel() {
    int w = (blockIdx.x * blockDim.x + threadIdx.x) >> 5;
    int lane = threadIdx.x & 31;
    if (w >= B * N) return;
    const float4* row = reinterpret_cast<const float4*>(&g_d2[(size_t)w * N]);
    float b0 = 3.4e38f, b1 = 3.4e38f, b2 = 3.4e38f, b3 = 3.4e38f, b4 = 3.4e38f;
#pragma unroll 4
    for (int q = lane; q < NQ; q += 32) {
        float4 v = row[q];
        INS5(v.x); INS5(v.y); INS5(v.z); INS5(v.w);
    }
    float s = 0.f;
#pragma unroll
    for (int t = 0; t < 5; t++) {
        float m = b0;
#pragma unroll
        for (int o = 16; o > 0; o >>= 1) m = fminf(m, __shfl_xor_sync(0xffffffffu, m, o));
        unsigned bal = __ballot_sync(0xffffffffu, b0 == m);
        if (lane == (__ffs(bal) - 1)) {
            b0 = b1; b1 = b2; b2 = b3; b3 = b4; b4 = 3.4e38f;
        }
        float d = sqrtf(m) / 16.0f;
        s = s + d * d;
    }
    if (lane == 0)
        g_dens[w] = expf(-(s / 5.0f)) + jax_uniform_noise(w) * 1e-6f;
}

__global__ void parent_kernel() {
    int w = (blockIdx.x * blockDim.x + threadIdx.x) >> 5;
    int lane = threadIdx.x & 31;
    if (w >= B * N) return;
    int b = w / N;
    float di = g_dens[w];
    const float4* row = reinterpret_cast<const float4*>(&g_d2[(size_t)w * N]);
    const float4* dr  = reinterpret_cast<const float4*>(&g_dens[(size_t)b * N]);
    float mn = 3.4e38f;
#pragma unroll 4
    for (int q = lane; q < NQ; q += 32) {
        float4 v = row[q];
        float4 dd = dr[q];
        if (dd.x > di) mn = fminf(mn, v.x);
        if (dd.y > di) mn = fminf(mn, v.y);
        if (dd.z > di) mn = fminf(mn, v.z);
        if (dd.w > di) mn = fminf(mn, v.w);
    }
#pragma unroll
    for (int o = 16; o > 0; o >>= 1) mn = fminf(mn, __shfl_xor_sync(0xffffffffu, mn, o));
    if (lane == 0) {
        float dmax = sqrtf(__uint_as_float(g_maxb[b])) / 16.0f;
        float dp = fminf(dmax, sqrtf(mn) / 16.0f);
        g_score[w] = dp * di;
    }
}

// per-batch top-50 with warp-shuffle reductions (lower index wins ties)
__global__ void topk_kernel() {
    int b = blockIdx.x;
    __shared__ float s[N];
    __shared__ float wv[32];
    __shared__ int   wix[32];
    int t = threadIdx.x, lane = t & 31, w = t >> 5;
    for (int i = t; i < N; i += 1024) s[i] = g_score[b * N + i];
    __syncthreads();
    for (int m = 0; m < NC; m++) {
        float bs = -3.4e38f;
        int   bi = N;
        for (int i = t; i < N; i += 1024) {
            float v = s[i];
            if (v > bs) { bs = v; bi = i; }
        }
#pragma unroll
        for (int o = 16; o > 0; o >>= 1) {
            float ov = __shfl_xor_sync(0xffffffffu, bs, o);
            int   oi = __shfl_xor_sync(0xffffffffu, bi, o);
            if (ov > bs || (ov == bs && oi < bi)) { bs = ov; bi = oi; }
        }
        if (lane == 0) { wv[w] = bs; wix[w] = bi; }
        __syncthreads();
        if (w == 0) {
            bs = wv[lane]; bi = wix[lane];
#pragma unroll
            for (int o = 16; o > 0; o >>= 1) {
                float ov = __shfl_xor_sync(0xffffffffu, bs, o);
                int   oi = __shfl_xor_sync(0xffffffffu, bi, o);
                if (ov > bs || (ov == bs && oi < bi)) { bs = ov; bi = oi; }
            }
            if (lane == 0) { g_idx[b * NC + m] = bi; s[bi] = -3.4e38f; }
        }
        __syncthreads();
    }
}

__global__ void gather_kernel(const float* __restrict__ x, float* __restrict__ out) {
    int g = blockIdx.x * blockDim.x + threadIdx.x;
    if (g >= B * C * NC) return;
    int m = g % NC;
    int c = (g / NC) % C;
    int b = g / (NC * C);
    int idx = g_idx[b * NC + m];
    out[g] = x[(size_t)b * C * N + (size_t)c * N + idx];
}

// ---------------- launch -----------------------------------------------------
extern "C" void kernel_launch(void* const* d_in, const int* in_sizes, int n_in,
                              void* d_out, int out_size) {
    const float* x = (const float*)d_in[0];
    float* out = (float*)d_out;

    cudaFuncSetAttribute(gram_kernel,
                         cudaFuncAttributeMaxDynamicSharedMemorySize, DSMEM_BYTES);

    init_kernel<<<1, 32>>>();
    sq_kernel<<<(B * N + 255) / 256, 256>>>(x);
    dim3 sg(ASEGS, B);
    split_kernel<<<sg, 256>>>(x);
    dim3 gg(NPAIRS, 1, B);
    gram_kernel<<<gg, 256, DSMEM_BYTES>>>(x);
    int rows = B * N;
    knn_kernel<<<(rows * 32 + 255) / 256, 256>>>();
    parent_kernel<<<(rows * 32 + 255) / 256, 256>>>();
    topk_kernel<<<B, 1024>>>();
    gather_kernel<<<(B * C * NC + 255) / 256, 256>>>(x, out);
}

// round 11
// speedup vs baseline: 1.6026x; 1.2231x over previous
#include <cuda_runtime.h>
#include <cstdint>

#define B 8
#define C 256
#define N 3136
#define NP 3200
#define NQ (N/4)
#define NC 50
#define TILE 128
#define KT 16
#define NT 25
#define NPAIRS (NT*(NT+1)/2)
#define ASEGS 200              // NP/16
#define BSEGS 400              // NP/8
#define DSMEM_BYTES 47104      // 11776 floats

// ---------------- scratch (static device globals: allocation-guard safe) ----
__device__ float g_d2[(size_t)B * N * N];
__device__ __align__(16) float g_ah[(size_t)B * ASEGS * 32 * 128];
__device__ __align__(16) float g_al[(size_t)B * ASEGS * 32 * 128];
__device__ __align__(16) float g_bh[(size_t)B * BSEGS * 32 * 64];
__device__ __align__(16) float g_bl[(size_t)B * BSEGS * 32 * 64];
__device__ float    g_sq[B * N];
__device__ float    g_dens[B * N];
__device__ float    g_score[B * N];
__device__ unsigned g_maxb[B];
__device__ int      g_idx[B * NC];

// ---------------- threefry-2x32 (JAX-compatible) ---------------------------
__device__ __forceinline__ uint32_t rotl32(uint32_t x, int r) {
    return (x << r) | (x >> (32 - r));
}

__device__ __forceinline__ void threefry2x32_k42(uint32_t x0, uint32_t x1,
                                                 uint32_t& o0, uint32_t& o1) {
    const uint32_t ks0 = 0u;
    const uint32_t ks1 = 42u;
    const uint32_t ks2 = 0x1BD11BDAu ^ 42u;
    x0 += ks0; x1 += ks1;
#define TF_RND(r) { x0 += x1; x1 = rotl32(x1, r); x1 ^= x0; }
    TF_RND(13) TF_RND(15) TF_RND(26) TF_RND(6)
    x0 += ks1; x1 += ks2 + 1u;
    TF_RND(17) TF_RND(29) TF_RND(16) TF_RND(24)
    x0 += ks2; x1 += ks0 + 2u;
    TF_RND(13) TF_RND(15) TF_RND(26) TF_RND(6)
    x0 += ks0; x1 += ks1 + 3u;
    TF_RND(17) TF_RND(29) TF_RND(16) TF_RND(24)
    x0 += ks1; x1 += ks2 + 4u;
    TF_RND(13) TF_RND(15) TF_RND(26) TF_RND(6)
    x0 += ks2; x1 += ks0 + 5u;
#undef TF_RND
    o0 = x0; o1 = x1;
}

__device__ __forceinline__ float jax_uniform_noise(int g) {
    const int half = (B * N) / 2;  // 12544
    uint32_t lane = (g < half) ? (uint32_t)g : (uint32_t)(g - half);
    uint32_t o0, o1;
    threefry2x32_k42(lane, lane + (uint32_t)half, o0, o1);
    uint32_t bits = (g < half) ? o0 : o1;
    return __uint_as_float((bits >> 9) | 0x3F800000u) - 1.0f;
}

// ---------------- tf32 + f32x2 helpers ---------------------------------------
__device__ __forceinline__ uint32_t tf32r(float x) {
    uint32_t y;
    asm("cvt.rna.tf32.f32 %0, %1;" : "=r"(y) : "f"(x));
    return y;
}

__device__ __forceinline__ void split1(float v, float& h, float& l) {
    float hf = __uint_as_float(tf32r(v));
    h = hf;
    l = __uint_as_float(tf32r(v - hf));
}

__device__ __forceinline__ void mma8(float d[4], const uint32_t a[4], const uint32_t b[2]) {
    asm volatile(
        "mma.sync.aligned.m16n8k8.row.col.f32.tf32.tf32.f32 "
        "{%0,%1,%2,%3}, {%4,%5,%6,%7}, {%8,%9}, {%0,%1,%2,%3};"
        : "+f"(d[0]), "+f"(d[1]), "+f"(d[2]), "+f"(d[3])
        : "r"(a[0]), "r"(a[1]), "r"(a[2]), "r"(a[3]), "r"(b[0]), "r"(b[1]));
}

__device__ __forceinline__ unsigned long long ffma2(unsigned long long a,
                                                    unsigned long long b,
                                                    unsigned long long c) {
    unsigned long long d;
    asm("fma.rn.f32x2 %0, %1, %2, %3;" : "=l"(d) : "l"(a), "l"(b), "l"(c));
    return d;
}

__device__ __forceinline__ unsigned long long dup2(float a) {
    unsigned long long d;
    asm("mov.b64 %0, {%1, %1};" : "=l"(d) : "f"(a));
    return d;
}

__device__ __forceinline__ void barg(int id, int cnt) {
    asm volatile("bar.sync %0, %1;" :: "r"(id), "r"(cnt) : "memory");
}

// ---------------- kernels ---------------------------------------------------
__global__ void init_kernel() {
    int t = threadIdx.x;
    if (t < B) g_maxb[t] = 0u;
}

__global__ void sq_kernel(const float* __restrict__ x) {
    int g = blockIdx.x * blockDim.x + threadIdx.x;
    if (g >= B * N) return;
    int b = g / N, n = g % N;
    const float* p = x + (size_t)b * C * N + n;
    float s = 0.f;
#pragma unroll 8
    for (int c = 0; c < C; c++) {
        float v = p[(size_t)c * N];
        s = fmaf(v, v, s);
    }
    g_sq[g] = s;
}

// transpose + tf32 hi/lo split into global fragment layouts (tensor operands)
__global__ void split_kernel(const float* __restrict__ x) {
    const int seg = blockIdx.x;
    const int b = blockIdx.y;
    const int row0 = seg * 16;
    __shared__ float sv[16][260];
    const int t = threadIdx.x;
#pragma unroll
    for (int i = 0; i < 16; i++) {
        int r = t & 15;
        int k = (t >> 4) + i * 16;
        int row = row0 + r;
        float v = (row < N) ? x[((size_t)b * C + k) * N + row] : 0.f;
        sv[r][k] = v;
    }
    __syncthreads();
#pragma unroll
    for (int j = 0; j < 4; j++) {
        int u = t + j * 256;
        int k8 = u >> 5, lane = u & 31;
        int rl = lane >> 2, tg = lane & 3;
        int k = k8 * 8 + tg;
        float4 hv, lv;
        split1(sv[rl][k],         hv.x, lv.x);
        split1(sv[rl + 8][k],     hv.y, lv.y);
        split1(sv[rl][k + 4],     hv.z, lv.z);
        split1(sv[rl + 8][k + 4], hv.w, lv.w);
        size_t base = (((size_t)b * ASEGS + seg) * 32 + k8) * 128 + lane * 4;
        *reinterpret_cast<float4*>(&g_ah[base]) = hv;
        *reinterpret_cast<float4*>(&g_al[base]) = lv;
    }
#pragma unroll
    for (int j = 0; j < 8; j++) {
        int u = t + j * 256;
        int cs = u >> 10, rem = u & 1023;
        int k8 = rem >> 5, lane = rem & 31;
        int col = cs * 8 + (lane >> 2), tg = lane & 3;
        int k = k8 * 8 + tg;
        float2 hv, lv;
        split1(sv[col][k],     hv.x, lv.x);
        split1(sv[col][k + 4], hv.y, lv.y);
        size_t base = (((size_t)b * BSEGS + seg * 2 + cs) * 32 + k8) * 64 + lane * 2;
        *reinterpret_cast<float2*>(&g_bh[base]) = hv;
        *reinterpret_cast<float2*>(&g_bl[base]) = lv;
    }
}

// INTRA-CTA HYBRID Gram: warps 0-5 = fp32 f32x2 path (cols 0..95),
// warps 6-7 = tf32x3 mma.sync path (cols 96..127). Named barriers per group.
// smem (floats): A [0,4096) 2buf x 16x128 ; B [4096,7168) 2buf x 16x96 ;
//                Ts reuses [0,2064) after fp32 mainloop ; TeS [7168,11776).
__global__ __launch_bounds__(256, 2) void gram_kernel(const float* __restrict__ x) {
    extern __shared__ float dynf[];
    __shared__ float red[256];

    const int b = blockIdx.z;
    int rem = blockIdx.x;
    int ti = 0;
    while (rem >= NT - ti) { rem -= NT - ti; ti++; }
    const int tj = ti + rem;
    const int i0 = ti * TILE, j0 = tj * TILE;

    const int tid = threadIdx.x, lane = tid & 31;
    const float* SQ = &g_sq[b * N];
    const size_t bN = (size_t)b * N;
    float tmax = 0.f;
    const float4 f40 = make_float4(0.f, 0.f, 0.f, 0.f);

    if (tid < 192) {
        // ===================== FP32 GROUP (6 warps, cols 0..95) ==============
        const float* X = x + (size_t)b * C * N;
        const int tx = tid % 12, ty = tid / 12;

        float4 pa0, pa1, pa2, pb0, pb1;
#define LDA(s, dst, k0) { int kk_=(s)>>5, f4_=(s)&31; int ic_=i0+f4_*4;       \
        dst = (ic_<N)? *reinterpret_cast<const float4*>(&X[(size_t)((k0)+kk_)*N+ic_]) : f40; }
#define LDB(s, dst, k0) { int kk_=(s)/24, c_=(s)%24; int jc_=j0+c_*4;         \
        dst = (jc_<N)? *reinterpret_cast<const float4*>(&X[(size_t)((k0)+kk_)*N+jc_]) : f40; }
#define LOADK(k0) { LDA(tid, pa0, k0); LDA(tid+192, pa1, k0);                  \
        if (tid < 128) LDA(tid+384, pa2, k0);                                  \
        LDB(tid, pb0, k0); LDB(tid+192, pb1, k0); }

        unsigned long long acc2[8][4];
#pragma unroll
        for (int r = 0; r < 8; r++)
#pragma unroll
            for (int c = 0; c < 4; c++) acc2[r][c] = 0ull;

        LOADK(0);
#pragma unroll 2
        for (int kt = 0; kt < C / KT; kt++) {
            const int boA = (kt & 1) * 2048;
            const int boB = 4096 + (kt & 1) * 1536;
            { int s=tid;     *reinterpret_cast<float4*>(&dynf[boA+(s>>5)*128+(s&31)*4]) = pa0; }
            { int s=tid+192; *reinterpret_cast<float4*>(&dynf[boA+(s>>5)*128+(s&31)*4]) = pa1; }
            if (tid < 128) { int s=tid+384; *reinterpret_cast<float4*>(&dynf[boA+(s>>5)*128+(s&31)*4]) = pa2; }
            { int s=tid;     *reinterpret_cast<float4*>(&dynf[boB+(s/24)*96+(s%24)*4]) = pb0; }
            { int s=tid+192; *reinterpret_cast<float4*>(&dynf[boB+(s/24)*96+(s%24)*4]) = pb1; }
            barg(1, 192);
            if (kt + 1 < C / KT) LOADK((kt + 1) * KT);
#pragma unroll
            for (int kk = 0; kk < KT; kk++) {
                float a[8];
                *reinterpret_cast<float4*>(&a[0]) =
                    *reinterpret_cast<float4*>(&dynf[boA + kk * 128 + ty * 8]);
                *reinterpret_cast<float4*>(&a[4]) =
                    *reinterpret_cast<float4*>(&dynf[boA + kk * 128 + ty * 8 + 4]);
                ulonglong2 bp0 = *reinterpret_cast<ulonglong2*>(&dynf[boB + kk * 96 + tx * 8]);
                ulonglong2 bp1 = *reinterpret_cast<ulonglong2*>(&dynf[boB + kk * 96 + tx * 8 + 4]);
#pragma unroll
                for (int r = 0; r < 8; r++) {
                    unsigned long long ad = dup2(a[r]);
                    acc2[r][0] = ffma2(ad, bp0.x, acc2[r][0]);
                    acc2[r][1] = ffma2(ad, bp0.y, acc2[r][1]);
                    acc2[r][2] = ffma2(ad, bp1.x, acc2[r][2]);
                    acc2[r][3] = ffma2(ad, bp1.y, acc2[r][3]);
                }
            }
            barg(1, 192);
        }
#undef LOADK
#undef LDB
#undef LDA

        float acc[8][8];
#pragma unroll
        for (int r = 0; r < 8; r++)
#pragma unroll
            for (int c = 0; c < 4; c++) {
                unsigned long long v = acc2[r][c];
                acc[r][2 * c]     = __uint_as_float((uint32_t)(v & 0xffffffffu));
                acc[r][2 * c + 1] = __uint_as_float((uint32_t)(v >> 32));
            }

        float sqi[8], sqj[8];
        const int jb = j0 + tx * 8;
        const bool jwr = (jb < N);
#pragma unroll
        for (int r = 0; r < 8; r++) {
            int gi = i0 + ty * 8 + r;
            sqi[r] = (gi < N) ? SQ[gi] : 0.f;
        }
#pragma unroll
        for (int c = 0; c < 8; c++) {
            int gj = jb + c;
            sqj[c] = (gj < N) ? SQ[gj] : 0.f;
        }
#pragma unroll
        for (int r = 0; r < 8; r++) {
#pragma unroll
            for (int c = 0; c < 8; c++)
                acc[r][c] = fmaxf(sqi[r] + sqj[c] - 2.f * acc[r][c], 0.f);
            int gi = i0 + ty * 8 + r;
            if (gi < N && jwr) {
#pragma unroll
                for (int c = 0; c < 8; c++) tmax = fmaxf(tmax, acc[r][c]);
                float* dst = &g_d2[(bN + gi) * N + jb];
                *reinterpret_cast<float4*>(dst)     = *reinterpret_cast<float4*>(&acc[r][0]);
                *reinterpret_cast<float4*>(dst + 4) = *reinterpret_cast<float4*>(&acc[r][4]);
            }
        }

        if (ti != tj) {
            float* Ts = dynf;    // 16 x 129, reuses A-buf region (fp32 group only)
            for (int s = 0; s < 6; s++) {
                barg(1, 192);
                if ((tx >> 1) == s) {
#pragma unroll
                    for (int c = 0; c < 8; c++)
#pragma unroll
                        for (int r = 0; r < 8; r++)
                            Ts[((tx & 1) * 8 + c) * 129 + ty * 8 + r] = acc[r][c];
                }
                barg(1, 192);
#pragma unroll
                for (int w2 = 0; w2 < 3; w2++) {
                    int slot = tid + 192 * w2;
                    if (slot < 512) {
                        int jr = slot >> 5, q4 = slot & 31;
                        int gj = j0 + s * 16 + jr, gi = i0 + q4 * 4;
                        if (gj < N && gi < N) {
                            float4 v = make_float4(Ts[jr * 129 + q4 * 4],
                                                   Ts[jr * 129 + q4 * 4 + 1],
                                                   Ts[jr * 129 + q4 * 4 + 2],
                                                   Ts[jr * 129 + q4 * 4 + 3]);
                            *reinterpret_cast<float4*>(&g_d2[(bN + gj) * N + gi]) = v;
                        }
                    }
                }
            }
        }
    } else {
        // ===================== TENSOR GROUP (2 warps, cols 96..127) ==========
        const int t2 = tid - 192;         // 0..63
        const int wr = t2 >> 5;           // 0..1 (row half)
        const int kq = lane & 3, rr = lane >> 2;
        float* TeS = dynf + 7168;         // 4608 floats, tensor-private

        const uint4* pah = reinterpret_cast<const uint4*>(
            g_ah + ((size_t)b * ASEGS + ti * 8 + wr * 4) * 4096) + lane;
        const uint4* pal = reinterpret_cast<const uint4*>(
            g_al + ((size_t)b * ASEGS + ti * 8 + wr * 4) * 4096) + lane;
        const uint2* pbh = reinterpret_cast<const uint2*>(
            g_bh + ((size_t)b * BSEGS + tj * 16 + 12) * 2048) + lane;
        const uint2* pbl = reinterpret_cast<const uint2*>(
            g_bl + ((size_t)b * BSEGS + tj * 16 + 12) * 2048) + lane;

        float D[4][4][4];
#pragma unroll
        for (int mf = 0; mf < 4; mf++)
#pragma unroll
            for (int nf = 0; nf < 4; nf++)
#pragma unroll
                for (int e = 0; e < 4; e++) D[mf][nf][e] = 0.f;

#pragma unroll 2
        for (int k8 = 0; k8 < 32; k8++) {
            uint4 AH[4], AL[4];
            uint2 BH[4], BL[4];
#pragma unroll
            for (int mf = 0; mf < 4; mf++) {
                AH[mf] = pah[mf * 1024];
                AL[mf] = pal[mf * 1024];
            }
#pragma unroll
            for (int nf = 0; nf < 4; nf++) {
                BH[nf] = pbh[nf * 1024];
                BL[nf] = pbl[nf * 1024];
            }
            pah += 32; pal += 32; pbh += 32; pbl += 32;
#pragma unroll
            for (int mf = 0; mf < 4; mf++) {
                uint32_t ah[4] = {AH[mf].x, AH[mf].y, AH[mf].z, AH[mf].w};
                uint32_t al[4] = {AL[mf].x, AL[mf].y, AL[mf].z, AL[mf].w};
#pragma unroll
                for (int nf = 0; nf < 4; nf++) {
                    uint32_t bh[2] = {BH[nf].x, BH[nf].y};
                    uint32_t bl[2] = {BL[nf].x, BL[nf].y};
                    mma8(D[mf][nf], ah, bl);
                    mma8(D[mf][nf], al, bh);
                    mma8(D[mf][nf], ah, bh);
                }
            }
        }

        // stage straight (pitch 36), write d2 rows i0.., cols j0+96..+127
#pragma unroll
        for (int mf = 0; mf < 4; mf++)
#pragma unroll
            for (int nf = 0; nf < 4; nf++) {
                int r0 = wr * 64 + mf * 16 + rr;
                int cl = nf * 8 + 2 * kq;
                TeS[r0 * 36 + cl]       = D[mf][nf][0];
                TeS[r0 * 36 + cl + 1]   = D[mf][nf][1];
                TeS[(r0 + 8) * 36 + cl]     = D[mf][nf][2];
                TeS[(r0 + 8) * 36 + cl + 1] = D[mf][nf][3];
            }
        barg(2, 64);
#pragma unroll
        for (int i = 0; i < 16; i++) {
            int slot = t2 + 64 * i;
            int row = slot >> 3, c4 = slot & 7;
            int gi = i0 + row, gj = j0 + 96 + c4 * 4;
            if (gi < N && gj < N) {
                float sqi = SQ[gi];
                float4 v = *reinterpret_cast<float4*>(&TeS[row * 36 + c4 * 4]);
                float4 o;
                o.x = fmaxf(sqi + SQ[gj + 0] - 2.f * v.x, 0.f);
                o.y = fmaxf(sqi + SQ[gj + 1] - 2.f * v.y, 0.f);
                o.z = fmaxf(sqi + SQ[gj + 2] - 2.f * v.z, 0.f);
                o.w = fmaxf(sqi + SQ[gj + 3] - 2.f * v.w, 0.f);
                tmax = fmaxf(tmax, fmaxf(fmaxf(o.x, o.y), fmaxf(o.z, o.w)));
                *reinterpret_cast<float4*>(&g_d2[(bN + gi) * N + gj]) = o;
            }
        }

        if (ti != tj) {
            barg(2, 64);
            // stage transposed (pitch 132), write d2 rows j0+96.., cols i0..+127
#pragma unroll
            for (int mf = 0; mf < 4; mf++)
#pragma unroll
                for (int nf = 0; nf < 4; nf++) {
                    int r0 = wr * 64 + mf * 16 + rr;
                    int cl = nf * 8 + 2 * kq;
                    TeS[cl * 132 + r0]           = D[mf][nf][0];
                    TeS[(cl + 1) * 132 + r0]     = D[mf][nf][1];
                    TeS[cl * 132 + r0 + 8]       = D[mf][nf][2];
                    TeS[(cl + 1) * 132 + r0 + 8] = D[mf][nf][3];
                }
            barg(2, 64);
#pragma unroll
            for (int i = 0; i < 16; i++) {
                int slot = t2 + 64 * i;
                int jr = slot >> 5, q4 = slot & 31;
                int gj = j0 + 96 + jr, gi = i0 + q4 * 4;
                if (gj < N && gi < N) {
                    float sqj = SQ[gj];
                    float4 v = *reinterpret_cast<float4*>(&TeS[jr * 132 + q4 * 4]);
                    float4 o;
                    o.x = fmaxf(SQ[gi + 0] + sqj - 2.f * v.x, 0.f);
                    o.y = fmaxf(SQ[gi + 1] + sqj - 2.f * v.y, 0.f);
                    o.z = fmaxf(SQ[gi + 2] + sqj - 2.f * v.z, 0.f);
                    o.w = fmaxf(SQ[gi + 3] + sqj - 2.f * v.w, 0.f);
                    *reinterpret_cast<float4*>(&g_d2[(bN + gj) * N + gi]) = o;
                }
            }
        }
    }

    __syncthreads();
    red[tid] = tmax;
    __syncthreads();
    for (int o = 128; o > 0; o >>= 1) {
        if (tid < o) red[tid] = fmaxf(red[tid], red[tid + o]);
        __syncthreads();
    }
    if (tid == 0) atomicMax(&g_maxb[b], __float_as_uint(red[0]));
}

// branchless sorted-5 insert
#define INS5(v) {                                   \
        float w_ = (v), t_;                         \
        t_ = fminf(b0, w_); w_ = fmaxf(b0, w_); b0 = t_; \
        t_ = fminf(b1, w_); w_ = fmaxf(b1, w_); b1 = t_; \
        t_ = fminf(b2, w_); w_ = fmaxf(b2, w_); b2 = t_; \
        t_ = fminf(b3, w_); w_ = fmaxf(b3, w_); b3 = t_; \
        b4 = fminf(b4, w_);                         \
    }

__global__ void knn_kernel() {
    int w = (blockIdx.x * blockDim.x + threadIdx.x) >> 5;
    int lane = threadIdx.x & 31;
    if (w >= B * N) return;
    const float4* row = reinterpret_cast<const float4*>(&g_d2[(size_t)w * N]);
    float b0 = 3.4e38f, b1 = 3.4e38f, b2 = 3.4e38f, b3 = 3.4e38f, b4 = 3.4e38f;
#pragma unroll 4
    for (int q = lane; q < NQ; q += 32) {
        float4 v = row[q];
        INS5(v.x); INS5(v.y); INS5(v.z); INS5(v.w);
    }
    float s = 0.f;
#pragma unroll
    for (int t = 0; t < 5; t++) {
        float m = b0;
#pragma unroll
        for (int o = 16; o > 0; o >>= 1) m = fminf(m, __shfl_xor_sync(0xffffffffu, m, o));
        unsigned bal = __ballot_sync(0xffffffffu, b0 == m);
        if (lane == (__ffs(bal) - 1)) {
            b0 = b1; b1 = b2; b2 = b3; b3 = b4; b4 = 3.4e38f;
        }
        float d = sqrtf(m) / 16.0f;
        s = s + d * d;
    }
    if (lane == 0)
        g_dens[w] = expf(-(s / 5.0f)) + jax_uniform_noise(w) * 1e-6f;
}

__global__ void parent_kernel() {
    int w = (blockIdx.x * blockDim.x + threadIdx.x) >> 5;
    int lane = threadIdx.x & 31;
    if (w >= B * N) return;
    int b = w / N;
    float di = g_dens[w];
    const float4* row = reinterpret_cast<const float4*>(&g_d2[(size_t)w * N]);
    const float4* dr  = reinterpret_cast<const float4*>(&g_dens[(size_t)b * N]);
    float mn = 3.4e38f;
#pragma unroll 4
    for (int q = lane; q < NQ; q += 32) {
        float4 v = row[q];
        float4 dd = dr[q];
        if (dd.x > di) mn = fminf(mn, v.x);
        if (dd.y > di) mn = fminf(mn, v.y);
        if (dd.z > di) mn = fminf(mn, v.z);
        if (dd.w > di) mn = fminf(mn, v.w);
    }
#pragma unroll
    for (int o = 16; o > 0; o >>= 1) mn = fminf(mn, __shfl_xor_sync(0xffffffffu, mn, o));
    if (lane == 0) {
        float dmax = sqrtf(__uint_as_float(g_maxb[b])) / 16.0f;
        float dp = fminf(dmax, sqrtf(mn) / 16.0f);
        g_score[w] = dp * di;
    }
}

// per-batch top-50 with warp-shuffle reductions (lower index wins ties)
__global__ void topk_kernel() {
    int b = blockIdx.x;
    __shared__ float s[N];
    __shared__ float wv[32];
    __shared__ int   wix[32];
    int t = threadIdx.x, lane = t & 31, w = t >> 5;
    for (int i = t; i < N; i += 1024) s[i] = g_score[b * N + i];
    __syncthreads();
    for (int m = 0; m < NC; m++) {
        float bs = -3.4e38f;
        int   bi = N;
        for (int i = t; i < N; i += 1024) {
            float v = s[i];
            if (v > bs) { bs = v; bi = i; }
        }
#pragma unroll
        for (int o = 16; o > 0; o >>= 1) {
            float ov = __shfl_xor_sync(0xffffffffu, bs, o);
            int   oi = __shfl_xor_sync(0xffffffffu, bi, o);
            if (ov > bs || (ov == bs && oi < bi)) { bs = ov; bi = oi; }
        }
        if (lane == 0) { wv[w] = bs; wix[w] = bi; }
        __syncthreads();
        if (w == 0) {
            bs = wv[lane]; bi = wix[lane];
#pragma unroll
            for (int o = 16; o > 0; o >>= 1) {
                float ov = __shfl_xor_sync(0xffffffffu, bs, o);
                int   oi = __shfl_xor_sync(0xffffffffu, bi, o);
                if (ov > bs || (ov == bs && oi < bi)) { bs = ov; bi = oi; }
            }
            if (lane == 0) { g_idx[b * NC + m] = bi; s[bi] = -3.4e38f; }
        }
        __syncthreads();
    }
}

__global__ void gather_kernel(const float* __restrict__ x, float* __restrict__ out) {
    int g = blockIdx.x * blockDim.x + threadIdx.x;
    if (g >= B * C * NC) return;
    int m = g % NC;
    int c = (g / NC) % C;
    int b = g / (NC * C);
    int idx = g_idx[b * NC + m];
    out[g] = x[(size_t)b * C * N + (size_t)c * N + idx];
}

// ---------------- launch -----------------------------------------------------
extern "C" void kernel_launch(void* const* d_in, const int* in_sizes, int n_in,
                              void* d_out, int out_size) {
    const float* x = (const float*)d_in[0];
    float* out = (float*)d_out;

    cudaFuncSetAttribute(gram_kernel,
                         cudaFuncAttributeMaxDynamicSharedMemorySize, DSMEM_BYTES);

    init_kernel<<<1, 32>>>();
    sq_kernel<<<(B * N + 255) / 256, 256>>>(x);
    dim3 sg(ASEGS, B);
    split_kernel<<<sg, 256>>>(x);
    dim3 gg(NPAIRS, 1, B);
    gram_kernel<<<gg, 256, DSMEM_BYTES>>>(x);
    int rows = B * N;
    knn_kernel<<<(rows * 32 + 255) / 256, 256>>>();
    parent_kernel<<<(rows * 32 + 255) / 256, 256>>>();
    topk_kernel<<<B, 1024>>>();
    gather_kernel<<<(B * C * NC + 255) / 256, 256>>>(x, out);
}